// round 1
// baseline (speedup 1.0000x reference)
#include <cuda_runtime.h>
#include <cstdint>

// Problem constants
#define BATCH     32
#define SEQ       1024
#define CTXD      1024
#define DMODEL    768
#define NHEAD     8
#define HDIM      96          // 768 / 8
#define NQ        256

// ---------------- device scratch (no allocations allowed) ----------------
__device__ float g_xk[BATCH * SEQ * CTXD];              // 128 MB  LN(x)
__device__ float g_qln[NQ * DMODEL];                    // LN(query)
__device__ float g_qh[NQ * DMODEL];                     // q projection
__device__ float g_kh[BATCH * SEQ * DMODEL];            // 96 MB
__device__ float g_vh[BATCH * SEQ * DMODEL];            // 96 MB
__device__ float g_bias[BATCH * SEQ];                   // log(size)+mask
__device__ float g_scores[BATCH * NHEAD * NQ * SEQ];    // 256 MB
__device__ float g_attnout[BATCH * NQ * DMODEL];        // 25 MB

// ---------------- LayerNorm (one block per row) ----------------
__global__ void ln_kernel(const float* __restrict__ x,
                          const float* __restrict__ w,
                          const float* __restrict__ b,
                          float* __restrict__ out, int ncols) {
    __shared__ float s1[32], s2[32];
    const size_t row = blockIdx.x;
    const float* xr = x + row * (size_t)ncols;
    float* orow = out + row * (size_t)ncols;

    float sum = 0.f, sumsq = 0.f;
    for (int i = threadIdx.x; i < ncols; i += blockDim.x) {
        float v = xr[i];
        sum += v; sumsq += v * v;
    }
    #pragma unroll
    for (int o = 16; o; o >>= 1) {
        sum   += __shfl_xor_sync(0xffffffffu, sum, o);
        sumsq += __shfl_xor_sync(0xffffffffu, sumsq, o);
    }
    int wid = threadIdx.x >> 5, lid = threadIdx.x & 31;
    if (lid == 0) { s1[wid] = sum; s2[wid] = sumsq; }
    __syncthreads();
    if (threadIdx.x < 32) {
        int nw = blockDim.x >> 5;
        float a = (lid < nw) ? s1[lid] : 0.f;
        float c = (lid < nw) ? s2[lid] : 0.f;
        #pragma unroll
        for (int o = 16; o; o >>= 1) {
            a += __shfl_xor_sync(0xffffffffu, a, o);
            c += __shfl_xor_sync(0xffffffffu, c, o);
        }
        if (lid == 0) { s1[0] = a; s2[0] = c; }
    }
    __syncthreads();
    float inv_n = 1.0f / (float)ncols;
    float mu  = s1[0] * inv_n;
    float var = s2[0] * inv_n - mu * mu;
    float rs  = rsqrtf(var + 1e-5f);
    for (int i = threadIdx.x; i < ncols; i += blockDim.x) {
        orow[i] = (xr[i] - mu) * rs * w[i] + b[i];
    }
}

// ---------------- bias = log(max(size,>=0.5->size else 1)) + mask ----------------
__global__ void bias_kernel(const float* __restrict__ size_in,
                            const float* __restrict__ mask,
                            float* __restrict__ bias, int n) {
    int i = blockIdx.x * blockDim.x + threadIdx.x;
    if (i < n) {
        float s = size_in[i];
        s = (s < 0.5f) ? 1.0f : s;
        bias[i] = logf(s) + mask[i];
    }
}

// ---------------- generic tiled GEMM (64x64x16, 4x4 microtile) ----------------
// C[M,N] = alpha * A[M,K] * op(B) + bias_n[N]
//   TRANS_B = true  : B is [N,K] row-major (both operands K-contiguous)
//   TRANS_B = false : B is [K,N] row-major
#define TBM 64
#define TBN 64
#define TBK 16
#define SPAD 4

template<bool TRANS_B>
__device__ __forceinline__ void gemm_tile(
    const float* __restrict__ A, int lda,
    const float* __restrict__ B, int ldb,
    float* __restrict__ C, int ldc,
    int M, int N, int K, float alpha,
    const float* __restrict__ bias_n)
{
    __shared__ __align__(16) float As[TBK][TBM + SPAD];
    __shared__ __align__(16) float Bs[TBK][TBN + SPAD];

    const int m0 = blockIdx.y * TBM;
    const int n0 = blockIdx.x * TBN;
    const int t  = threadIdx.x;            // 256 threads
    const int tx = t & 15;
    const int ty = t >> 4;

    float acc[4][4] = {};

    for (int k0 = 0; k0 < K; k0 += TBK) {
        // Load A tile (64x16) -> As[k][m]
        {
            int col  = t & 15;      // k
            int rowb = t >> 4;      // m base
            #pragma unroll
            for (int i = 0; i < 4; i++) {
                int r  = rowb + i * 16;
                int gm = m0 + r, gk = k0 + col;
                As[col][r] = (gm < M && gk < K) ? A[(size_t)gm * lda + gk] : 0.f;
            }
        }
        // Load B tile -> Bs[k][n]
        if (TRANS_B) {
            int col  = t & 15;      // k
            int rowb = t >> 4;      // n base
            #pragma unroll
            for (int i = 0; i < 4; i++) {
                int nn = rowb + i * 16;
                int gn = n0 + nn, gk = k0 + col;
                Bs[col][nn] = (gn < N && gk < K) ? B[(size_t)gn * ldb + gk] : 0.f;
            }
        } else {
            int nn   = t & 63;      // n
            int rowb = t >> 6;      // k base (4 per pass)
            #pragma unroll
            for (int i = 0; i < 4; i++) {
                int k  = rowb + i * 4;
                int gk = k0 + k, gn = n0 + nn;
                Bs[k][nn] = (gk < K && gn < N) ? B[(size_t)gk * ldb + gn] : 0.f;
            }
        }
        __syncthreads();

        #pragma unroll
        for (int kk = 0; kk < TBK; kk++) {
            float4 av = *reinterpret_cast<const float4*>(&As[kk][ty * 4]);
            float4 bv = *reinterpret_cast<const float4*>(&Bs[kk][tx * 4]);
            float a[4] = {av.x, av.y, av.z, av.w};
            float b[4] = {bv.x, bv.y, bv.z, bv.w};
            #pragma unroll
            for (int i = 0; i < 4; i++)
                #pragma unroll
                for (int j = 0; j < 4; j++)
                    acc[i][j] += a[i] * b[j];
        }
        __syncthreads();
    }

    #pragma unroll
    for (int i = 0; i < 4; i++) {
        int gm = m0 + ty * 4 + i;
        if (gm >= M) continue;
        #pragma unroll
        for (int j = 0; j < 4; j++) {
            int gn = n0 + tx * 4 + j;
            if (gn >= N) continue;
            float v = alpha * acc[i][j];
            if (bias_n) v += bias_n[gn];
            C[(size_t)gm * ldc + gn] = v;
        }
    }
}

__global__ void __launch_bounds__(256)
gemm_nt_kernel(const float* __restrict__ A, int lda,
               const float* __restrict__ B, int ldb,
               float* __restrict__ C, int ldc,
               int M, int N, int K, float alpha,
               const float* __restrict__ bias_n) {
    gemm_tile<true>(A, lda, B, ldb, C, ldc, M, N, K, alpha, bias_n);
}

// scores[b,h,q,l] = scale * sum_d qh[q, h*96+d] * kh[(b*1024+l), h*96+d] + bias[b,l]
__global__ void __launch_bounds__(256)
scores_kernel(const float* __restrict__ qh, const float* __restrict__ kh,
              const float* __restrict__ biasBL, float* __restrict__ scores,
              float alpha) {
    int z = blockIdx.z;            // b*8 + h
    int b = z >> 3, h = z & 7;
    const float* A = qh + h * HDIM;                                   // [256, 96] lda=768
    const float* B = kh + (size_t)b * SEQ * DMODEL + h * HDIM;        // [1024, 96] ldb=768
    float* C = scores + (size_t)z * NQ * SEQ;                         // [256, 1024]
    gemm_tile<true>(A, DMODEL, B, DMODEL, C, SEQ, NQ, SEQ, HDIM, alpha,
                    biasBL + (size_t)b * SEQ);
}

// attnout[b,q,h*96+d] = sum_l P[z,q,l] * vh[(b*1024+l), h*96+d]
__global__ void __launch_bounds__(256)
av_kernel(const float* __restrict__ P, const float* __restrict__ vh,
          float* __restrict__ O) {
    int z = blockIdx.z;
    int b = z >> 3, h = z & 7;
    const float* A = P + (size_t)z * NQ * SEQ;                        // [256, 1024]
    const float* B = vh + (size_t)b * SEQ * DMODEL + h * HDIM;        // [1024, 96] ldb=768 (NN)
    float* C = O + (size_t)b * NQ * DMODEL + h * HDIM;                // ldc=768
    gemm_tile<false>(A, SEQ, B, DMODEL, C, DMODEL, NQ, HDIM, SEQ, 1.0f, nullptr);
}

// ---------------- softmax over rows of 1024 ----------------
__global__ void __launch_bounds__(256)
softmax1024_kernel(float* __restrict__ S) {
    __shared__ float red[32];
    size_t row = blockIdx.x;
    float4* r4 = reinterpret_cast<float4*>(S + row * (size_t)SEQ);
    int t = threadIdx.x;
    float4 v = r4[t];

    // --- max reduce ---
    float mx = fmaxf(fmaxf(v.x, v.y), fmaxf(v.z, v.w));
    #pragma unroll
    for (int o = 16; o; o >>= 1) mx = fmaxf(mx, __shfl_xor_sync(0xffffffffu, mx, o));
    int wid = t >> 5, lid = t & 31;
    if (lid == 0) red[wid] = mx;
    __syncthreads();
    if (t < 32) {
        float m = (lid < 8) ? red[lid] : -3.4e38f;
        #pragma unroll
        for (int o = 16; o; o >>= 1) m = fmaxf(m, __shfl_xor_sync(0xffffffffu, m, o));
        if (lid == 0) red[0] = m;
    }
    __syncthreads();
    mx = red[0];
    __syncthreads();

    // --- exp + sum reduce ---
    float4 e;
    e.x = __expf(v.x - mx); e.y = __expf(v.y - mx);
    e.z = __expf(v.z - mx); e.w = __expf(v.w - mx);
    float sum = e.x + e.y + e.z + e.w;
    #pragma unroll
    for (int o = 16; o; o >>= 1) sum += __shfl_xor_sync(0xffffffffu, sum, o);
    if (lid == 0) red[wid] = sum;
    __syncthreads();
    if (t < 32) {
        float s = (lid < 8) ? red[lid] : 0.f;
        #pragma unroll
        for (int o = 16; o; o >>= 1) s += __shfl_xor_sync(0xffffffffu, s, o);
        if (lid == 0) red[0] = s;
    }
    __syncthreads();
    float inv = 1.0f / red[0];
    e.x *= inv; e.y *= inv; e.z *= inv; e.w *= inv;
    r4[t] = e;
}

// ---------------- launch ----------------
extern "C" void kernel_launch(void* const* d_in, const int* in_sizes, int n_in,
                              void* d_out, int out_size) {
    const float* x     = (const float*)d_in[0];   // [32,1024,1024]
    const float* sizei = (const float*)d_in[1];   // [32,1024,1]
    const float* amask = (const float*)d_in[2];   // [32,1,1024]
    const float* query = (const float*)d_in[3];   // [256,768]
    const float* ln_q_w = (const float*)d_in[4];
    const float* ln_q_b = (const float*)d_in[5];
    const float* ln_k_w = (const float*)d_in[6];
    const float* ln_k_b = (const float*)d_in[7];
    const float* Wq = (const float*)d_in[8];      // [768,768]
    const float* Wk = (const float*)d_in[9];      // [768,1024]
    const float* Wv = (const float*)d_in[10];     // [768,1024]
    const float* bq = (const float*)d_in[11];
    const float* bk = (const float*)d_in[12];
    const float* bv = (const float*)d_in[13];
    const float* Wo = (const float*)d_in[14];     // [768,768]
    const float* bo = (const float*)d_in[15];
    float* out = (float*)d_out;                   // [32,256,768]

    float *xk, *qln, *qh, *kh, *vh, *bias, *scores, *attnout;
    cudaGetSymbolAddress((void**)&xk, g_xk);
    cudaGetSymbolAddress((void**)&qln, g_qln);
    cudaGetSymbolAddress((void**)&qh, g_qh);
    cudaGetSymbolAddress((void**)&kh, g_kh);
    cudaGetSymbolAddress((void**)&vh, g_vh);
    cudaGetSymbolAddress((void**)&bias, g_bias);
    cudaGetSymbolAddress((void**)&scores, g_scores);
    cudaGetSymbolAddress((void**)&attnout, g_attnout);

    const float scale = 0.10206207261596575f;  // 1/sqrt(96)

    // 1) LayerNorms
    ln_kernel<<<BATCH * SEQ, 256>>>(x, ln_k_w, ln_k_b, xk, CTXD);
    ln_kernel<<<NQ, 256>>>(query, ln_q_w, ln_q_b, qln, DMODEL);

    // 2) additive bias
    bias_kernel<<<(BATCH * SEQ + 255) / 256, 256>>>(sizei, amask, bias, BATCH * SEQ);

    // 3) projections
    gemm_nt_kernel<<<dim3(DMODEL / TBN, NQ / TBM), 256>>>(
        qln, DMODEL, Wq, DMODEL, qh, DMODEL, NQ, DMODEL, DMODEL, 1.0f, bq);
    gemm_nt_kernel<<<dim3(DMODEL / TBN, BATCH * SEQ / TBM), 256>>>(
        xk, CTXD, Wk, CTXD, kh, DMODEL, BATCH * SEQ, DMODEL, CTXD, 1.0f, bk);
    gemm_nt_kernel<<<dim3(DMODEL / TBN, BATCH * SEQ / TBM), 256>>>(
        xk, CTXD, Wv, CTXD, vh, DMODEL, BATCH * SEQ, DMODEL, CTXD, 1.0f, bv);

    // 4) scores + bias  (batched over b*h)
    scores_kernel<<<dim3(SEQ / TBN, NQ / TBM, BATCH * NHEAD), 256>>>(
        qh, kh, bias, scores, scale);

    // 5) softmax over L
    softmax1024_kernel<<<BATCH * NHEAD * NQ, 256>>>(scores);

    // 6) attn @ V  (batched over b*h)
    av_kernel<<<dim3((HDIM + TBN - 1) / TBN, NQ / TBM, BATCH * NHEAD), 256>>>(
        scores, vh, attnout);

    // 7) output projection
    gemm_nt_kernel<<<dim3(DMODEL / TBN, BATCH * NQ / TBM), 256>>>(
        attnout, DMODEL, Wo, DMODEL, out, DMODEL, BATCH * NQ, DMODEL, DMODEL, 1.0f, bo);
}

// round 3
// speedup vs baseline: 1.6471x; 1.6471x over previous
#include <cuda_runtime.h>
#include <cuda_bf16.h>
#include <cstdint>

// Problem constants
#define BATCH     32
#define SEQ       1024
#define CTXD      1024
#define DMODEL    768
#define NHEAD     8
#define HDIM      96
#define NQ        256
#define MROWS     (BATCH * SEQ)   // 32768

// ============================ device scratch ============================
__device__ __nv_bfloat16 g_xhi[MROWS * CTXD];           // LN(x) hi
__device__ __nv_bfloat16 g_xlo[MROWS * CTXD];           // LN(x) lo
__device__ __nv_bfloat16 g_wkhi[DMODEL * CTXD];
__device__ __nv_bfloat16 g_wklo[DMODEL * CTXD];
__device__ __nv_bfloat16 g_wvhi[DMODEL * CTXD];
__device__ __nv_bfloat16 g_wvlo[DMODEL * CTXD];
__device__ __nv_bfloat16 g_wohi[DMODEL * DMODEL];
__device__ __nv_bfloat16 g_wolo[DMODEL * DMODEL];
__device__ __nv_bfloat16 g_aohi[BATCH * NQ * DMODEL];   // attnout split
__device__ __nv_bfloat16 g_aolo[BATCH * NQ * DMODEL];
__device__ float g_qln[NQ * DMODEL];
__device__ float g_qh[NQ * DMODEL];
__device__ float g_kh[MROWS * DMODEL];
__device__ float g_vh[MROWS * DMODEL];
__device__ float g_bias[MROWS];
__device__ float g_scores[BATCH * NHEAD * NQ * SEQ];
__device__ float g_attnout[BATCH * NQ * DMODEL];

// ============================ mma helpers ============================
__device__ __forceinline__ uint32_t smem_u32(const void* p) {
    uint32_t a;
    asm("{ .reg .u64 t; cvta.to.shared.u64 t, %1; cvt.u32.u64 %0, t; }" : "=r"(a) : "l"(p));
    return a;
}
__device__ __forceinline__ void ldm_x4(uint32_t* r, uint32_t addr) {
    asm volatile("ldmatrix.sync.aligned.m8n8.x4.shared.b16 {%0,%1,%2,%3}, [%4];"
                 : "=r"(r[0]), "=r"(r[1]), "=r"(r[2]), "=r"(r[3]) : "r"(addr));
}
__device__ __forceinline__ void mma16816(float* c, const uint32_t* a, const uint32_t* b) {
    asm volatile("mma.sync.aligned.m16n8k16.row.col.f32.bf16.bf16.f32 "
                 "{%0,%1,%2,%3}, {%4,%5,%6,%7}, {%8,%9}, {%0,%1,%2,%3};"
                 : "+f"(c[0]), "+f"(c[1]), "+f"(c[2]), "+f"(c[3])
                 : "r"(a[0]), "r"(a[1]), "r"(a[2]), "r"(a[3]), "r"(b[0]), "r"(b[1]));
}

// ============================ split-bf16 tensor GEMM ============================
// C[M,N] = (Ahi+Alo)[M,K] * (Bhi+Blo)[N,K]^T + bias_n, dropping lo*lo.
// Grid: (N/128, M/128). 256 threads, warp tile 32x64.
#define LDS_BF 40   // smem row stride in bf16 (80 bytes; odd 16B-granule stride)

__global__ void __launch_bounds__(256, 1)
gemm_bf16x3_nt(const __nv_bfloat16* __restrict__ Ahi, const __nv_bfloat16* __restrict__ Alo,
               const __nv_bfloat16* __restrict__ Bhi, const __nv_bfloat16* __restrict__ Blo,
               const float* __restrict__ bias_n, float* __restrict__ C,
               int K, int ldc) {
    __shared__ __align__(16) __nv_bfloat16 sA[2][128 * LDS_BF];  // [hi/lo]
    __shared__ __align__(16) __nv_bfloat16 sB[2][128 * LDS_BF];

    const int tid  = threadIdx.x;
    const int wid  = tid >> 5;
    const int lane = tid & 31;
    const int m0 = blockIdx.y * 128;
    const int n0 = blockIdx.x * 128;
    const int wm = (wid & 3) * 32;   // warp m offset within CTA
    const int wn = (wid >> 2) * 64;  // warp n offset within CTA

    // ldmatrix smem byte addresses (per-lane), as u32 offsets
    const uint32_t aB = smem_u32(&sA[0][0]);
    const uint32_t bB = smem_u32(&sB[0][0]);
    // A: tile (mi in {0,1}): row = wm + mi*16 + (lane&15), colB = (lane>>4)*8
    const uint32_t aRow = (uint32_t)(wm + (lane & 15)) * LDS_BF + (uint32_t)(lane >> 4) * 8u;
    // B: group g: row = wn + g*16 + (lane&7) + (lane>>4)*8, colB = ((lane>>3)&1)*8
    const uint32_t bRow = (uint32_t)(wn + (lane & 7) + ((lane >> 4) * 8)) * LDS_BF
                        + (uint32_t)((lane >> 3) & 1) * 8u;

    float acc[2][8][4];
    #pragma unroll
    for (int i = 0; i < 2; i++)
        #pragma unroll
        for (int j = 0; j < 8; j++)
            #pragma unroll
            for (int k = 0; k < 4; k++) acc[i][j][k] = 0.f;

    const int r  = tid >> 2;       // load row (0..63 per half)
    const int cc = tid & 3;        // 16B column

    for (int k0 = 0; k0 < K; k0 += 32) {
        // ---- load 4 tiles (128x32 bf16 each) ----
        {
            const __nv_bfloat16* gAh = Ahi + (size_t)(m0) * K + k0;
            const __nv_bfloat16* gAl = Alo + (size_t)(m0) * K + k0;
            const __nv_bfloat16* gBh = Bhi + (size_t)(n0) * K + k0;
            const __nv_bfloat16* gBl = Blo + (size_t)(n0) * K + k0;
            #pragma unroll
            for (int h = 0; h < 2; h++) {
                int rr = r + h * 64;
                uint32_t so = (uint32_t)rr * LDS_BF + (uint32_t)cc * 8u;
                size_t go = (size_t)rr * K + cc * 8;
                *reinterpret_cast<uint4*>(&sA[0][so]) = *reinterpret_cast<const uint4*>(gAh + go);
                *reinterpret_cast<uint4*>(&sA[1][so]) = *reinterpret_cast<const uint4*>(gAl + go);
                *reinterpret_cast<uint4*>(&sB[0][so]) = *reinterpret_cast<const uint4*>(gBh + go);
                *reinterpret_cast<uint4*>(&sB[1][so]) = *reinterpret_cast<const uint4*>(gBl + go);
            }
        }
        __syncthreads();

        #pragma unroll
        for (int ks = 0; ks < 2; ks++) {
            const uint32_t kcol = (uint32_t)ks * 16u;
            uint32_t ahi[2][4], alo[2][4], b[4][4];
            #pragma unroll
            for (int mi = 0; mi < 2; mi++) {
                uint32_t off = (aRow + (uint32_t)mi * 16u * LDS_BF + kcol) * 2u;
                ldm_x4(ahi[mi], aB + off);
                ldm_x4(alo[mi], aB + 10240u + off);
            }
            // Bhi: HH + LH
            #pragma unroll
            for (int g = 0; g < 4; g++) {
                uint32_t off = (bRow + (uint32_t)g * 16u * LDS_BF + kcol) * 2u;
                ldm_x4(b[g], bB + off);
            }
            #pragma unroll
            for (int mi = 0; mi < 2; mi++)
                #pragma unroll
                for (int nj = 0; nj < 8; nj++) {
                    const uint32_t* bf = &b[nj >> 1][(nj & 1) * 2];
                    mma16816(acc[mi][nj], ahi[mi], bf);
                    mma16816(acc[mi][nj], alo[mi], bf);
                }
            // Blo: HL
            #pragma unroll
            for (int g = 0; g < 4; g++) {
                uint32_t off = (bRow + (uint32_t)g * 16u * LDS_BF + kcol) * 2u;
                ldm_x4(b[g], bB + 10240u + off);
            }
            #pragma unroll
            for (int mi = 0; mi < 2; mi++)
                #pragma unroll
                for (int nj = 0; nj < 8; nj++)
                    mma16816(acc[mi][nj], ahi[mi], &b[nj >> 1][(nj & 1) * 2]);
        }
        __syncthreads();
    }

    // ---- epilogue ----
    #pragma unroll
    for (int mi = 0; mi < 2; mi++) {
        int gm = m0 + wm + mi * 16 + (lane >> 2);
        #pragma unroll
        for (int nj = 0; nj < 8; nj++) {
            int gn = n0 + wn + nj * 8 + (lane & 3) * 2;
            float b0 = bias_n ? bias_n[gn]     : 0.f;
            float b1 = bias_n ? bias_n[gn + 1] : 0.f;
            float2 v0 = { acc[mi][nj][0] + b0, acc[mi][nj][1] + b1 };
            float2 v1 = { acc[mi][nj][2] + b0, acc[mi][nj][3] + b1 };
            *reinterpret_cast<float2*>(C + (size_t)gm * ldc + gn) = v0;
            *reinterpret_cast<float2*>(C + (size_t)(gm + 8) * ldc + gn) = v1;
        }
    }
}

// ============================ LayerNorm kernels ============================
__device__ __forceinline__ void ln_stats(const float* __restrict__ xr, int ncols,
                                         float& mu, float& rs,
                                         float* s1, float* s2) {
    float sum = 0.f, sumsq = 0.f;
    for (int i = threadIdx.x; i < ncols; i += blockDim.x) {
        float v = xr[i];
        sum += v; sumsq += v * v;
    }
    #pragma unroll
    for (int o = 16; o; o >>= 1) {
        sum   += __shfl_xor_sync(0xffffffffu, sum, o);
        sumsq += __shfl_xor_sync(0xffffffffu, sumsq, o);
    }
    int wid = threadIdx.x >> 5, lid = threadIdx.x & 31;
    if (lid == 0) { s1[wid] = sum; s2[wid] = sumsq; }
    __syncthreads();
    if (threadIdx.x < 32) {
        int nw = blockDim.x >> 5;
        float a = (lid < nw) ? s1[lid] : 0.f;
        float c = (lid < nw) ? s2[lid] : 0.f;
        #pragma unroll
        for (int o = 16; o; o >>= 1) {
            a += __shfl_xor_sync(0xffffffffu, a, o);
            c += __shfl_xor_sync(0xffffffffu, c, o);
        }
        if (lid == 0) { s1[0] = a; s2[0] = c; }
    }
    __syncthreads();
    float inv_n = 1.0f / (float)ncols;
    mu = s1[0] * inv_n;
    float var = s2[0] * inv_n - mu * mu;
    rs = rsqrtf(var + 1e-5f);
}

__global__ void ln_kernel(const float* __restrict__ x,
                          const float* __restrict__ w,
                          const float* __restrict__ b,
                          float* __restrict__ out, int ncols) {
    __shared__ float s1[32], s2[32];
    const size_t row = blockIdx.x;
    const float* xr = x + row * (size_t)ncols;
    float mu, rs;
    ln_stats(xr, ncols, mu, rs, s1, s2);
    float* orow = out + row * (size_t)ncols;
    for (int i = threadIdx.x; i < ncols; i += blockDim.x)
        orow[i] = (xr[i] - mu) * rs * w[i] + b[i];
}

__global__ void ln_split_kernel(const float* __restrict__ x,
                                const float* __restrict__ w,
                                const float* __restrict__ b,
                                __nv_bfloat16* __restrict__ hi,
                                __nv_bfloat16* __restrict__ lo, int ncols) {
    __shared__ float s1[32], s2[32];
    const size_t row = blockIdx.x;
    const float* xr = x + row * (size_t)ncols;
    float mu, rs;
    ln_stats(xr, ncols, mu, rs, s1, s2);
    __nv_bfloat16* hrow = hi + row * (size_t)ncols;
    __nv_bfloat16* lrow = lo + row * (size_t)ncols;
    for (int i = threadIdx.x; i < ncols; i += blockDim.x) {
        float y = (xr[i] - mu) * rs * w[i] + b[i];
        __nv_bfloat16 h = __float2bfloat16(y);
        hrow[i] = h;
        lrow[i] = __float2bfloat16(y - __bfloat162float(h));
    }
}

__global__ void split_kernel(const float* __restrict__ x,
                             __nv_bfloat16* __restrict__ hi,
                             __nv_bfloat16* __restrict__ lo, int n) {
    int i = blockIdx.x * blockDim.x + threadIdx.x;
    if (i < n) {
        float v = x[i];
        __nv_bfloat16 h = __float2bfloat16(v);
        hi[i] = h;
        lo[i] = __float2bfloat16(v - __bfloat162float(h));
    }
}

__global__ void bias_kernel(const float* __restrict__ size_in,
                            const float* __restrict__ mask,
                            float* __restrict__ bias, int n) {
    int i = blockIdx.x * blockDim.x + threadIdx.x;
    if (i < n) {
        float s = size_in[i];
        s = (s < 0.5f) ? 1.0f : s;
        bias[i] = logf(s) + mask[i];
    }
}

// ============================ SIMT GEMM (scores / AV / Q-proj) ============================
#define TBM 64
#define TBN 64
#define TBK 16
#define SPAD 4

template<bool TRANS_B>
__device__ __forceinline__ void gemm_tile(
    const float* __restrict__ A, int lda,
    const float* __restrict__ B, int ldb,
    float* __restrict__ C, int ldc,
    int M, int N, int K, float alpha,
    const float* __restrict__ bias_n)
{
    __shared__ __align__(16) float As[TBK][TBM + SPAD];
    __shared__ __align__(16) float Bs[TBK][TBN + SPAD];

    const int m0 = blockIdx.y * TBM;
    const int n0 = blockIdx.x * TBN;
    const int t  = threadIdx.x;
    const int tx = t & 15;
    const int ty = t >> 4;

    float acc[4][4] = {};

    for (int k0 = 0; k0 < K; k0 += TBK) {
        {
            int col  = t & 15;
            int rowb = t >> 4;
            #pragma unroll
            for (int i = 0; i < 4; i++) {
                int rr  = rowb + i * 16;
                int gm = m0 + rr, gk = k0 + col;
                As[col][rr] = (gm < M && gk < K) ? A[(size_t)gm * lda + gk] : 0.f;
            }
        }
        if (TRANS_B) {
            int col  = t & 15;
            int rowb = t >> 4;
            #pragma unroll
            for (int i = 0; i < 4; i++) {
                int nn = rowb + i * 16;
                int gn = n0 + nn, gk = k0 + col;
                Bs[col][nn] = (gn < N && gk < K) ? B[(size_t)gn * ldb + gk] : 0.f;
            }
        } else {
            int nn   = t & 63;
            int rowb = t >> 6;
            #pragma unroll
            for (int i = 0; i < 4; i++) {
                int k  = rowb + i * 4;
                int gk = k0 + k, gn = n0 + nn;
                Bs[k][nn] = (gk < K && gn < N) ? B[(size_t)gk * ldb + gn] : 0.f;
            }
        }
        __syncthreads();

        #pragma unroll
        for (int kk = 0; kk < TBK; kk++) {
            float4 av = *reinterpret_cast<const float4*>(&As[kk][ty * 4]);
            float4 bv = *reinterpret_cast<const float4*>(&Bs[kk][tx * 4]);
            float a[4] = {av.x, av.y, av.z, av.w};
            float b[4] = {bv.x, bv.y, bv.z, bv.w};
            #pragma unroll
            for (int i = 0; i < 4; i++)
                #pragma unroll
                for (int j = 0; j < 4; j++)
                    acc[i][j] += a[i] * b[j];
        }
        __syncthreads();
    }

    #pragma unroll
    for (int i = 0; i < 4; i++) {
        int gm = m0 + ty * 4 + i;
        if (gm >= M) continue;
        #pragma unroll
        for (int j = 0; j < 4; j++) {
            int gn = n0 + tx * 4 + j;
            if (gn >= N) continue;
            float v = alpha * acc[i][j];
            if (bias_n) v += bias_n[gn];
            C[(size_t)gm * ldc + gn] = v;
        }
    }
}

__global__ void __launch_bounds__(256)
gemm_nt_kernel(const float* __restrict__ A, int lda,
               const float* __restrict__ B, int ldb,
               float* __restrict__ C, int ldc,
               int M, int N, int K, float alpha,
               const float* __restrict__ bias_n) {
    gemm_tile<true>(A, lda, B, ldb, C, ldc, M, N, K, alpha, bias_n);
}

__global__ void __launch_bounds__(256)
scores_kernel(const float* __restrict__ qh, const float* __restrict__ kh,
              const float* __restrict__ biasBL, float* __restrict__ scores,
              float alpha) {
    int z = blockIdx.z;
    int b = z >> 3, h = z & 7;
    const float* A = qh + h * HDIM;
    const float* B = kh + (size_t)b * SEQ * DMODEL + h * HDIM;
    float* C = scores + (size_t)z * NQ * SEQ;
    gemm_tile<true>(A, DMODEL, B, DMODEL, C, SEQ, NQ, SEQ, HDIM, alpha,
                    biasBL + (size_t)b * SEQ);
}

__global__ void __launch_bounds__(256)
av_kernel(const float* __restrict__ P, const float* __restrict__ vh,
          float* __restrict__ O) {
    int z = blockIdx.z;
    int b = z >> 3, h = z & 7;
    const float* A = P + (size_t)z * NQ * SEQ;
    const float* B = vh + (size_t)b * SEQ * DMODEL + h * HDIM;
    float* C = O + (size_t)b * NQ * DMODEL + h * HDIM;
    gemm_tile<false>(A, SEQ, B, DMODEL, C, DMODEL, NQ, HDIM, SEQ, 1.0f, nullptr);
}

// ============================ softmax over rows of 1024 ============================
__global__ void __launch_bounds__(256)
softmax1024_kernel(float* __restrict__ S) {
    __shared__ float red[32];
    size_t row = blockIdx.x;
    float4* r4 = reinterpret_cast<float4*>(S + row * (size_t)SEQ);
    int t = threadIdx.x;
    float4 v = r4[t];

    float mx = fmaxf(fmaxf(v.x, v.y), fmaxf(v.z, v.w));
    #pragma unroll
    for (int o = 16; o; o >>= 1) mx = fmaxf(mx, __shfl_xor_sync(0xffffffffu, mx, o));
    int wid = t >> 5, lid = t & 31;
    if (lid == 0) red[wid] = mx;
    __syncthreads();
    if (t < 32) {
        float m = (lid < 8) ? red[lid] : -3.4e38f;
        #pragma unroll
        for (int o = 16; o; o >>= 1) m = fmaxf(m, __shfl_xor_sync(0xffffffffu, m, o));
        if (lid == 0) red[0] = m;
    }
    __syncthreads();
    mx = red[0];
    __syncthreads();

    float4 e;
    e.x = __expf(v.x - mx); e.y = __expf(v.y - mx);
    e.z = __expf(v.z - mx); e.w = __expf(v.w - mx);
    float sum = e.x + e.y + e.z + e.w;
    #pragma unroll
    for (int o = 16; o; o >>= 1) sum += __shfl_xor_sync(0xffffffffu, sum, o);
    if (lid == 0) red[wid] = sum;
    __syncthreads();
    if (t < 32) {
        float s = (lid < 8) ? red[lid] : 0.f;
        #pragma unroll
        for (int o = 16; o; o >>= 1) s += __shfl_xor_sync(0xffffffffu, s, o);
        if (lid == 0) red[0] = s;
    }
    __syncthreads();
    float inv = 1.0f / red[0];
    e.x *= inv; e.y *= inv; e.z *= inv; e.w *= inv;
    r4[t] = e;
}

// ============================ launch ============================
extern "C" void kernel_launch(void* const* d_in, const int* in_sizes, int n_in,
                              void* d_out, int out_size) {
    const float* x     = (const float*)d_in[0];
    const float* sizei = (const float*)d_in[1];
    const float* amask = (const float*)d_in[2];
    const float* query = (const float*)d_in[3];
    const float* ln_q_w = (const float*)d_in[4];
    const float* ln_q_b = (const float*)d_in[5];
    const float* ln_k_w = (const float*)d_in[6];
    const float* ln_k_b = (const float*)d_in[7];
    const float* Wq = (const float*)d_in[8];
    const float* Wk = (const float*)d_in[9];
    const float* Wv = (const float*)d_in[10];
    const float* bq = (const float*)d_in[11];
    const float* bk = (const float*)d_in[12];
    const float* bv = (const float*)d_in[13];
    const float* Wo = (const float*)d_in[14];
    const float* bo = (const float*)d_in[15];
    float* out = (float*)d_out;

    __nv_bfloat16 *xhi, *xlo, *wkhi, *wklo, *wvhi, *wvlo, *wohi, *wolo, *aohi, *aolo;
    float *qln, *qh, *kh, *vh, *bias, *scores, *attnout;
    cudaGetSymbolAddress((void**)&xhi, g_xhi);
    cudaGetSymbolAddress((void**)&xlo, g_xlo);
    cudaGetSymbolAddress((void**)&wkhi, g_wkhi);
    cudaGetSymbolAddress((void**)&wklo, g_wklo);
    cudaGetSymbolAddress((void**)&wvhi, g_wvhi);
    cudaGetSymbolAddress((void**)&wvlo, g_wvlo);
    cudaGetSymbolAddress((void**)&wohi, g_wohi);
    cudaGetSymbolAddress((void**)&wolo, g_wolo);
    cudaGetSymbolAddress((void**)&aohi, g_aohi);
    cudaGetSymbolAddress((void**)&aolo, g_aolo);
    cudaGetSymbolAddress((void**)&qln, g_qln);
    cudaGetSymbolAddress((void**)&qh, g_qh);
    cudaGetSymbolAddress((void**)&kh, g_kh);
    cudaGetSymbolAddress((void**)&vh, g_vh);
    cudaGetSymbolAddress((void**)&bias, g_bias);
    cudaGetSymbolAddress((void**)&scores, g_scores);
    cudaGetSymbolAddress((void**)&attnout, g_attnout);

    const float scale = 0.10206207261596575f;  // 1/sqrt(96)

    // 1) LN of x -> split bf16 hi/lo ; LN of query -> f32
    ln_split_kernel<<<MROWS, 256>>>(x, ln_k_w, ln_k_b, xhi, xlo, CTXD);
    ln_kernel<<<NQ, 256>>>(query, ln_q_w, ln_q_b, qln, DMODEL);

    // 2) split weights
    split_kernel<<<(DMODEL * CTXD + 255) / 256, 256>>>(Wk, wkhi, wklo, DMODEL * CTXD);
    split_kernel<<<(DMODEL * CTXD + 255) / 256, 256>>>(Wv, wvhi, wvlo, DMODEL * CTXD);
    split_kernel<<<(DMODEL * DMODEL + 255) / 256, 256>>>(Wo, wohi, wolo, DMODEL * DMODEL);

    // 3) additive bias
    bias_kernel<<<(MROWS + 255) / 256, 256>>>(sizei, amask, bias, MROWS);

    // 4) K/V projections on tensor cores (mma.sync split-bf16)
    {
        dim3 grid(DMODEL / 128, MROWS / 128);   // (6, 256)
        gemm_bf16x3_nt<<<grid, 256>>>(xhi, xlo, wkhi, wklo, bk, kh, CTXD, DMODEL);
        gemm_bf16x3_nt<<<grid, 256>>>(xhi, xlo, wvhi, wvlo, bv, vh, CTXD, DMODEL);
    }

    // 5) Q projection (SIMT, tiny)
    gemm_nt_kernel<<<dim3(DMODEL / TBN, NQ / TBM), 256>>>(
        qln, DMODEL, Wq, DMODEL, qh, DMODEL, NQ, DMODEL, DMODEL, 1.0f, bq);

    // 6) scores + bias
    scores_kernel<<<dim3(SEQ / TBN, NQ / TBM, BATCH * NHEAD), 256>>>(
        qh, kh, bias, scores, scale);

    // 7) softmax
    softmax1024_kernel<<<BATCH * NHEAD * NQ, 256>>>(scores);

    // 8) attn @ V
    av_kernel<<<dim3((HDIM + TBN - 1) / TBN, NQ / TBM, BATCH * NHEAD), 256>>>(
        scores, vh, attnout);

    // 9) output projection on tensor cores
    split_kernel<<<(BATCH * NQ * DMODEL + 255) / 256, 256>>>(attnout, aohi, aolo,
                                                             BATCH * NQ * DMODEL);
    gemm_bf16x3_nt<<<dim3(DMODEL / 128, BATCH * NQ / 128), 256>>>(
        aohi, aolo, wohi, wolo, bo, out, DMODEL, DMODEL);
}

// round 4
// speedup vs baseline: 2.4961x; 1.5154x over previous
#include <cuda_runtime.h>
#include <cuda_bf16.h>
#include <cstdint>

#define BATCH     32
#define SEQ       1024
#define CTXD      1024
#define DMODEL    768
#define NHEAD     8
#define HDIM      96
#define NQ        256
#define MROWS     (BATCH * SEQ)   // 32768
#define NZ        (BATCH * NHEAD) // 256

typedef __nv_bfloat16 bf16;
typedef __nv_bfloat162 bf162;

// ============================ device scratch ============================
__device__ bf16 g_xhi[MROWS * CTXD];
__device__ bf16 g_xlo[MROWS * CTXD];
__device__ bf16 g_wkhi[DMODEL * CTXD];
__device__ bf16 g_wklo[DMODEL * CTXD];
__device__ bf16 g_wvhi[DMODEL * CTXD];
__device__ bf16 g_wvlo[DMODEL * CTXD];
__device__ bf16 g_wohi[DMODEL * DMODEL];
__device__ bf16 g_wolo[DMODEL * DMODEL];
__device__ bf16 g_khhi[MROWS * DMODEL];
__device__ bf16 g_khlo[MROWS * DMODEL];
__device__ bf16 g_vhhi[MROWS * DMODEL];
__device__ bf16 g_vhlo[MROWS * DMODEL];
__device__ bf16 g_qhhi[NQ * DMODEL];
__device__ bf16 g_qhlo[NQ * DMODEL];
__device__ bf16 g_phi[NZ * NQ * SEQ];
__device__ bf16 g_plo[NZ * NQ * SEQ];
__device__ bf16 g_aohi[BATCH * NQ * DMODEL];
__device__ bf16 g_aolo[BATCH * NQ * DMODEL];
__device__ float g_qln[NQ * DMODEL];
__device__ float g_qh[NQ * DMODEL];
__device__ float g_bias[MROWS];
__device__ float g_scores[NZ * NQ * SEQ];   // 256 MB

// ============================ asm helpers ============================
__device__ __forceinline__ uint32_t smem_u32(const void* p) {
    uint32_t a;
    asm("{ .reg .u64 t; cvta.to.shared.u64 t, %1; cvt.u32.u64 %0, t; }" : "=r"(a) : "l"(p));
    return a;
}
__device__ __forceinline__ void ldm_x4(uint32_t* r, uint32_t addr) {
    asm volatile("ldmatrix.sync.aligned.m8n8.x4.shared.b16 {%0,%1,%2,%3}, [%4];"
                 : "=r"(r[0]), "=r"(r[1]), "=r"(r[2]), "=r"(r[3]) : "r"(addr));
}
__device__ __forceinline__ void ldm_x4_t(uint32_t* r, uint32_t addr) {
    asm volatile("ldmatrix.sync.aligned.m8n8.x4.trans.shared.b16 {%0,%1,%2,%3}, [%4];"
                 : "=r"(r[0]), "=r"(r[1]), "=r"(r[2]), "=r"(r[3]) : "r"(addr));
}
__device__ __forceinline__ void mma16816(float* c, const uint32_t* a, const uint32_t* b) {
    asm volatile("mma.sync.aligned.m16n8k16.row.col.f32.bf16.bf16.f32 "
                 "{%0,%1,%2,%3}, {%4,%5,%6,%7}, {%8,%9}, {%0,%1,%2,%3};"
                 : "+f"(c[0]), "+f"(c[1]), "+f"(c[2]), "+f"(c[3])
                 : "r"(a[0]), "r"(a[1]), "r"(a[2]), "r"(a[3]), "r"(b[0]), "r"(b[1]));
}
__device__ __forceinline__ void cp16(uint32_t dst, const void* src) {
    asm volatile("cp.async.cg.shared.global [%0], [%1], 16;" :: "r"(dst), "l"(src));
}
#define CP_COMMIT() asm volatile("cp.async.commit_group;")
#define CP_WAIT0()  asm volatile("cp.async.wait_group 0;")

__device__ __forceinline__ void split2(float v0, float v1, bf162& h2, bf162& l2) {
    bf16 h0 = __float2bfloat16(v0);
    bf16 h1 = __float2bfloat16(v1);
    h2 = bf162(h0, h1);
    l2 = bf162(__float2bfloat16(v0 - __bfloat162float(h0)),
               __float2bfloat16(v1 - __bfloat162float(h1)));
}

// ============================ generalized split-bf16 NT GEMM ============================
// C[M,N] = alpha*((Ahi+Alo)[m, k] * (Bhi+Blo)[n, k]^T) + bias_n  (3-term, drop lo*lo)
// CTA tile 128x128, k-chunk 32, double-buffered cp.async. 256 threads, warp tile 32x64.
// Dynamic smem layout (bytes): A: buf*20480 + term*10240 ; B: 40960 + buf*20480 + term*10240
#define G3_SMEM 81920
#define LDS_BF 40

template<int EPI>  // 0: fp32 out, 1: split bf16 out
__device__ __forceinline__ void gemm3_dev(
    char* smem,
    const bf16* __restrict__ Ahi, const bf16* __restrict__ Alo, int lda,
    const bf16* __restrict__ Bhi, const bf16* __restrict__ Blo, int ldb,
    int K, int m0, int n0, float alpha, const float* __restrict__ bias_n,
    float* __restrict__ Cf, bf16* __restrict__ Chi, bf16* __restrict__ Clo, int ldc)
{
    const int tid  = threadIdx.x;
    const int wid  = tid >> 5;
    const int lane = tid & 31;
    const int wm = (wid & 3) * 32;
    const int wn = (wid >> 2) * 64;

    const uint32_t smBase = smem_u32(smem);
    const uint32_t aRow = (uint32_t)(wm + (lane & 15)) * LDS_BF + (uint32_t)(lane >> 4) * 8u;
    const uint32_t bRow = (uint32_t)(wn + (lane & 7) + ((lane >> 4) * 8)) * LDS_BF
                        + (uint32_t)((lane >> 3) & 1) * 8u;

    float acc[2][8][4];
    #pragma unroll
    for (int i = 0; i < 2; i++)
        #pragma unroll
        for (int j = 0; j < 8; j++)
            #pragma unroll
            for (int k = 0; k < 4; k++) acc[i][j][k] = 0.f;

    const int r  = tid >> 2;
    const int cc = tid & 3;
    const int nchunks = K >> 5;

    // load chunk helper (8x cp.async 16B per thread)
    auto load_chunk = [&](int k0, int buf) {
        uint32_t aB = smBase + (uint32_t)buf * 20480u;
        uint32_t bB = smBase + 40960u + (uint32_t)buf * 20480u;
        #pragma unroll
        for (int h = 0; h < 2; h++) {
            int rr = r + h * 64;
            uint32_t so = ((uint32_t)rr * LDS_BF + (uint32_t)cc * 8u) * 2u;
            size_t ga = (size_t)(m0 + rr) * lda + k0 + cc * 8;
            size_t gb = (size_t)(n0 + rr) * ldb + k0 + cc * 8;
            cp16(aB + so,           Ahi + ga);
            cp16(aB + 10240u + so,  Alo + ga);
            cp16(bB + so,           Bhi + gb);
            cp16(bB + 10240u + so,  Blo + gb);
        }
    };

    load_chunk(0, 0);
    CP_COMMIT();

    for (int c = 0; c < nchunks; c++) {
        CP_WAIT0();
        __syncthreads();
        if (c + 1 < nchunks) { load_chunk((c + 1) << 5, (c + 1) & 1); CP_COMMIT(); }

        uint32_t aB = smBase + (uint32_t)(c & 1) * 20480u;
        uint32_t bB = smBase + 40960u + (uint32_t)(c & 1) * 20480u;
        #pragma unroll
        for (int ks = 0; ks < 2; ks++) {
            const uint32_t kcol = (uint32_t)ks * 16u;
            uint32_t ahi[2][4], alo[2][4], b[4][4];
            #pragma unroll
            for (int mi = 0; mi < 2; mi++) {
                uint32_t off = (aRow + (uint32_t)mi * 16u * LDS_BF + kcol) * 2u;
                ldm_x4(ahi[mi], aB + off);
                ldm_x4(alo[mi], aB + 10240u + off);
            }
            #pragma unroll
            for (int g = 0; g < 4; g++) {
                uint32_t off = (bRow + (uint32_t)g * 16u * LDS_BF + kcol) * 2u;
                ldm_x4(b[g], bB + off);
            }
            #pragma unroll
            for (int mi = 0; mi < 2; mi++)
                #pragma unroll
                for (int nj = 0; nj < 8; nj++) {
                    const uint32_t* bf = &b[nj >> 1][(nj & 1) * 2];
                    mma16816(acc[mi][nj], ahi[mi], bf);
                    mma16816(acc[mi][nj], alo[mi], bf);
                }
            #pragma unroll
            for (int g = 0; g < 4; g++) {
                uint32_t off = (bRow + (uint32_t)g * 16u * LDS_BF + kcol) * 2u;
                ldm_x4(b[g], bB + 10240u + off);
            }
            #pragma unroll
            for (int mi = 0; mi < 2; mi++)
                #pragma unroll
                for (int nj = 0; nj < 8; nj++)
                    mma16816(acc[mi][nj], ahi[mi], &b[nj >> 1][(nj & 1) * 2]);
        }
        __syncthreads();
    }

    // epilogue
    #pragma unroll
    for (int mi = 0; mi < 2; mi++) {
        int gm = m0 + wm + mi * 16 + (lane >> 2);
        #pragma unroll
        for (int nj = 0; nj < 8; nj++) {
            int gn = n0 + wn + nj * 8 + (lane & 3) * 2;
            float b0 = bias_n ? bias_n[gn]     : 0.f;
            float b1 = bias_n ? bias_n[gn + 1] : 0.f;
            float v00 = alpha * acc[mi][nj][0] + b0;
            float v01 = alpha * acc[mi][nj][1] + b1;
            float v10 = alpha * acc[mi][nj][2] + b0;
            float v11 = alpha * acc[mi][nj][3] + b1;
            if (EPI == 0) {
                *reinterpret_cast<float2*>(Cf + (size_t)gm * ldc + gn)       = make_float2(v00, v01);
                *reinterpret_cast<float2*>(Cf + (size_t)(gm + 8) * ldc + gn) = make_float2(v10, v11);
            } else {
                bf162 h2, l2;
                split2(v00, v01, h2, l2);
                *reinterpret_cast<bf162*>(Chi + (size_t)gm * ldc + gn) = h2;
                *reinterpret_cast<bf162*>(Clo + (size_t)gm * ldc + gn) = l2;
                split2(v10, v11, h2, l2);
                *reinterpret_cast<bf162*>(Chi + (size_t)(gm + 8) * ldc + gn) = h2;
                *reinterpret_cast<bf162*>(Clo + (size_t)(gm + 8) * ldc + gn) = l2;
            }
        }
    }
}

// ---- wrappers ----
__global__ void __launch_bounds__(256, 1)
kv_gemm(const bf16* __restrict__ Ahi, const bf16* __restrict__ Alo,
        const bf16* __restrict__ Bhi, const bf16* __restrict__ Blo,
        const float* __restrict__ bias_n, bf16* __restrict__ Chi, bf16* __restrict__ Clo) {
    extern __shared__ char smem[];
    gemm3_dev<1>(smem, Ahi, Alo, CTXD, Bhi, Blo, CTXD, CTXD,
                 blockIdx.y * 128, blockIdx.x * 128, 1.0f, bias_n,
                 nullptr, Chi, Clo, DMODEL);
}

__global__ void __launch_bounds__(256, 1)
oproj_gemm(const bf16* __restrict__ Ahi, const bf16* __restrict__ Alo,
           const bf16* __restrict__ Bhi, const bf16* __restrict__ Blo,
           const float* __restrict__ bias_n, float* __restrict__ C) {
    extern __shared__ char smem[];
    gemm3_dev<0>(smem, Ahi, Alo, DMODEL, Bhi, Blo, DMODEL, DMODEL,
                 blockIdx.y * 128, blockIdx.x * 128, 1.0f, bias_n,
                 C, nullptr, nullptr, DMODEL);
}

__global__ void __launch_bounds__(256, 1)
scores_gemm(const bf16* __restrict__ Qhi, const bf16* __restrict__ Qlo,
            const bf16* __restrict__ Khi, const bf16* __restrict__ Klo,
            const float* __restrict__ biasBL, float* __restrict__ scores, float alpha) {
    extern __shared__ char smem[];
    int z = blockIdx.z;
    int b = z >> 3, h = z & 7;
    gemm3_dev<0>(smem,
                 Qhi + h * HDIM, Qlo + h * HDIM, DMODEL,
                 Khi + (size_t)b * SEQ * DMODEL + h * HDIM,
                 Klo + (size_t)b * SEQ * DMODEL + h * HDIM, DMODEL,
                 HDIM, blockIdx.y * 128, blockIdx.x * 128, alpha,
                 biasBL + (size_t)b * SEQ,
                 scores + (size_t)z * NQ * SEQ, nullptr, nullptr, SEQ);
}

// ============================ AV tensor kernel ============================
// O[128m, 96n] = (Phi+Plo)[m, k=L] @ (Vhi+Vlo)[k=L, n]  (3-term)
// Dynamic smem: P: buf*20480 + term*10240 ; V: 40960 + buf*13312 + term*6656
#define AV_SMEM 67584
#define LDS_V 104

__global__ void __launch_bounds__(256, 1)
av_gemm(const bf16* __restrict__ Phi, const bf16* __restrict__ Plo,
        const bf16* __restrict__ Vhi, const bf16* __restrict__ Vlo,
        bf16* __restrict__ Ohi, bf16* __restrict__ Olo) {
    extern __shared__ char smem[];
    const int tid = threadIdx.x;
    const int wid = tid >> 5, lane = tid & 31;
    const int z = blockIdx.y;
    const int b = z >> 3, h = z & 7;
    const int m0 = blockIdx.x * 128;

    const bf16* Pb_hi = Phi + (size_t)z * NQ * SEQ;
    const bf16* Pb_lo = Plo + (size_t)z * NQ * SEQ;
    const bf16* Vb_hi = Vhi + (size_t)b * SEQ * DMODEL + h * HDIM;
    const bf16* Vb_lo = Vlo + (size_t)b * SEQ * DMODEL + h * HDIM;

    const uint32_t smBase = smem_u32(smem);
    const int wm = wid * 16;

    float acc[12][4];
    #pragma unroll
    for (int j = 0; j < 12; j++)
        #pragma unroll
        for (int k = 0; k < 4; k++) acc[j][k] = 0.f;

    auto load_chunk = [&](int k0, int buf) {
        uint32_t pB = smBase + (uint32_t)buf * 20480u;
        uint32_t vB = smBase + 40960u + (uint32_t)buf * 13312u;
        // P: 128 rows x 32 k, 2 terms
        {
            int i0 = tid;
            #pragma unroll
            for (int rep = 0; rep < 2; rep++) {
                int i = i0 + rep * 256;
                int row = i >> 2, c = i & 3;
                uint32_t so = ((uint32_t)row * LDS_BF + (uint32_t)c * 8u) * 2u;
                size_t go = (size_t)(m0 + row) * SEQ + k0 + c * 8;
                cp16(pB + so,          Pb_hi + go);
                cp16(pB + 10240u + so, Pb_lo + go);
            }
        }
        // V: 32 rows (k) x 96 cols (n) = 384 uint4 per term
        for (int i = tid; i < 384; i += 256) {
            int row = i / 12, c = i % 12;
            uint32_t so = ((uint32_t)row * LDS_V + (uint32_t)c * 8u) * 2u;
            size_t go = (size_t)(k0 + row) * DMODEL + c * 8;
            cp16(vB + so,         Vb_hi + go);
            cp16(vB + 6656u + so, Vb_lo + go);
        }
    };

    const uint32_t aRow = (uint32_t)(wm + (lane & 15)) * LDS_BF + (uint32_t)(lane >> 4) * 8u;
    const uint32_t vLaneRow = (uint32_t)((lane & 7) + ((lane >> 3) & 1) * 8);
    const uint32_t vLaneCol = (uint32_t)(lane >> 4) * 8u;

    load_chunk(0, 0);
    CP_COMMIT();

    const int nchunks = SEQ >> 5;  // 32
    for (int c = 0; c < nchunks; c++) {
        CP_WAIT0();
        __syncthreads();
        if (c + 1 < nchunks) { load_chunk((c + 1) << 5, (c + 1) & 1); CP_COMMIT(); }

        uint32_t pB = smBase + (uint32_t)(c & 1) * 20480u;
        uint32_t vB = smBase + 40960u + (uint32_t)(c & 1) * 13312u;
        #pragma unroll
        for (int ks = 0; ks < 2; ks++) {
            const uint32_t kcol = (uint32_t)ks * 16u;
            uint32_t ahi[4], alo[4], bv[4];
            {
                uint32_t off = (aRow + kcol) * 2u;
                ldm_x4(ahi, pB + off);
                ldm_x4(alo, pB + 10240u + off);
            }
            #pragma unroll
            for (int g = 0; g < 6; g++) {
                uint32_t nb = (uint32_t)g * 16u;
                uint32_t off = ((kcol + vLaneRow) * LDS_V + nb + vLaneCol) * 2u;
                ldm_x4_t(bv, vB + off);
                mma16816(acc[2 * g],     ahi, &bv[0]);
                mma16816(acc[2 * g + 1], ahi, &bv[2]);
                mma16816(acc[2 * g],     alo, &bv[0]);
                mma16816(acc[2 * g + 1], alo, &bv[2]);
                ldm_x4_t(bv, vB + 6656u + off);
                mma16816(acc[2 * g],     ahi, &bv[0]);
                mma16816(acc[2 * g + 1], ahi, &bv[2]);
            }
        }
        __syncthreads();
    }

    // epilogue: write split bf16 attnout at [(b*256+q), h*96+n]
    const int rr = lane >> 2, cp2 = (lane & 3) * 2;
    const int gm0 = m0 + wm + rr;
    #pragma unroll
    for (int j = 0; j < 12; j++) {
        int n = j * 8 + cp2;
        size_t o0 = ((size_t)(b * NQ + gm0)) * DMODEL + h * HDIM + n;
        size_t o1 = o0 + (size_t)8 * DMODEL;
        bf162 h2, l2;
        split2(acc[j][0], acc[j][1], h2, l2);
        *reinterpret_cast<bf162*>(Ohi + o0) = h2;
        *reinterpret_cast<bf162*>(Olo + o0) = l2;
        split2(acc[j][2], acc[j][3], h2, l2);
        *reinterpret_cast<bf162*>(Ohi + o1) = h2;
        *reinterpret_cast<bf162*>(Olo + o1) = l2;
    }
}

// ============================ LayerNorm / misc ============================
__device__ __forceinline__ void ln_stats(const float* __restrict__ xr, int ncols,
                                         float& mu, float& rs, float* s1, float* s2) {
    float sum = 0.f, sumsq = 0.f;
    for (int i = threadIdx.x; i < ncols; i += blockDim.x) {
        float v = xr[i];
        sum += v; sumsq += v * v;
    }
    #pragma unroll
    for (int o = 16; o; o >>= 1) {
        sum   += __shfl_xor_sync(0xffffffffu, sum, o);
        sumsq += __shfl_xor_sync(0xffffffffu, sumsq, o);
    }
    int wid = threadIdx.x >> 5, lid = threadIdx.x & 31;
    if (lid == 0) { s1[wid] = sum; s2[wid] = sumsq; }
    __syncthreads();
    if (threadIdx.x < 32) {
        int nw = blockDim.x >> 5;
        float a = (lid < nw) ? s1[lid] : 0.f;
        float c = (lid < nw) ? s2[lid] : 0.f;
        #pragma unroll
        for (int o = 16; o; o >>= 1) {
            a += __shfl_xor_sync(0xffffffffu, a, o);
            c += __shfl_xor_sync(0xffffffffu, c, o);
        }
        if (lid == 0) { s1[0] = a; s2[0] = c; }
    }
    __syncthreads();
    float inv_n = 1.0f / (float)ncols;
    mu = s1[0] * inv_n;
    float var = s2[0] * inv_n - mu * mu;
    rs = rsqrtf(var + 1e-5f);
}

__global__ void ln_kernel(const float* __restrict__ x, const float* __restrict__ w,
                          const float* __restrict__ b, float* __restrict__ out, int ncols) {
    __shared__ float s1[32], s2[32];
    const size_t row = blockIdx.x;
    const float* xr = x + row * (size_t)ncols;
    float mu, rs;
    ln_stats(xr, ncols, mu, rs, s1, s2);
    float* orow = out + row * (size_t)ncols;
    for (int i = threadIdx.x; i < ncols; i += blockDim.x)
        orow[i] = (xr[i] - mu) * rs * w[i] + b[i];
}

__global__ void ln_split_kernel(const float* __restrict__ x, const float* __restrict__ w,
                                const float* __restrict__ b,
                                bf16* __restrict__ hi, bf16* __restrict__ lo, int ncols) {
    __shared__ float s1[32], s2[32];
    const size_t row = blockIdx.x;
    const float* xr = x + row * (size_t)ncols;
    float mu, rs;
    ln_stats(xr, ncols, mu, rs, s1, s2);
    bf16* hrow = hi + row * (size_t)ncols;
    bf16* lrow = lo + row * (size_t)ncols;
    for (int i = threadIdx.x; i < ncols; i += blockDim.x) {
        float y = (xr[i] - mu) * rs * w[i] + b[i];
        bf16 hh = __float2bfloat16(y);
        hrow[i] = hh;
        lrow[i] = __float2bfloat16(y - __bfloat162float(hh));
    }
}

__global__ void split_kernel(const float* __restrict__ x,
                             bf16* __restrict__ hi, bf16* __restrict__ lo, int n) {
    int i = blockIdx.x * blockDim.x + threadIdx.x;
    if (i < n) {
        float v = x[i];
        bf16 h = __float2bfloat16(v);
        hi[i] = h;
        lo[i] = __float2bfloat16(v - __bfloat162float(h));
    }
}

__global__ void bias_kernel(const float* __restrict__ size_in, const float* __restrict__ mask,
                            float* __restrict__ bias, int n) {
    int i = blockIdx.x * blockDim.x + threadIdx.x;
    if (i < n) {
        float s = size_in[i];
        s = (s < 0.5f) ? 1.0f : s;
        bias[i] = logf(s) + mask[i];
    }
}

// ============================ SIMT GEMM (Q-proj only) ============================
#define TBM 64
#define TBN 64
#define TBK 16
#define SPAD 4

__global__ void __launch_bounds__(256)
gemm_nt_kernel(const float* __restrict__ A, int lda,
               const float* __restrict__ B, int ldb,
               float* __restrict__ C, int ldc,
               int M, int N, int K, float alpha, const float* __restrict__ bias_n) {
    __shared__ __align__(16) float As[TBK][TBM + SPAD];
    __shared__ __align__(16) float Bs[TBK][TBN + SPAD];
    const int m0 = blockIdx.y * TBM;
    const int n0 = blockIdx.x * TBN;
    const int t  = threadIdx.x;
    const int tx = t & 15, ty = t >> 4;
    float acc[4][4] = {};
    for (int k0 = 0; k0 < K; k0 += TBK) {
        {
            int col = t & 15, rowb = t >> 4;
            #pragma unroll
            for (int i = 0; i < 4; i++) {
                int rr = rowb + i * 16;
                As[col][rr] = A[(size_t)(m0 + rr) * lda + k0 + col];
            }
        }
        {
            int col = t & 15, rowb = t >> 4;
            #pragma unroll
            for (int i = 0; i < 4; i++) {
                int nn = rowb + i * 16;
                Bs[col][nn] = B[(size_t)(n0 + nn) * ldb + k0 + col];
            }
        }
        __syncthreads();
        #pragma unroll
        for (int kk = 0; kk < TBK; kk++) {
            float4 av = *reinterpret_cast<const float4*>(&As[kk][ty * 4]);
            float4 bv = *reinterpret_cast<const float4*>(&Bs[kk][tx * 4]);
            float a[4] = {av.x, av.y, av.z, av.w};
            float b[4] = {bv.x, bv.y, bv.z, bv.w};
            #pragma unroll
            for (int i = 0; i < 4; i++)
                #pragma unroll
                for (int j = 0; j < 4; j++)
                    acc[i][j] += a[i] * b[j];
        }
        __syncthreads();
    }
    #pragma unroll
    for (int i = 0; i < 4; i++) {
        int gm = m0 + ty * 4 + i;
        #pragma unroll
        for (int j = 0; j < 4; j++) {
            int gn = n0 + tx * 4 + j;
            float v = alpha * acc[i][j];
            if (bias_n) v += bias_n[gn];
            C[(size_t)gm * ldc + gn] = v;
        }
    }
}

// ============================ softmax (fp32 in, split bf16 out) ============================
__global__ void __launch_bounds__(256)
softmax_split_kernel(const float* __restrict__ S, bf16* __restrict__ Phi, bf16* __restrict__ Plo) {
    __shared__ float red[32];
    size_t row = blockIdx.x;
    const float4* r4 = reinterpret_cast<const float4*>(S + row * (size_t)SEQ);
    int t = threadIdx.x;
    float4 v = r4[t];

    float mx = fmaxf(fmaxf(v.x, v.y), fmaxf(v.z, v.w));
    #pragma unroll
    for (int o = 16; o; o >>= 1) mx = fmaxf(mx, __shfl_xor_sync(0xffffffffu, mx, o));
    int wid = t >> 5, lid = t & 31;
    if (lid == 0) red[wid] = mx;
    __syncthreads();
    if (t < 32) {
        float m = (lid < 8) ? red[lid] : -3.4e38f;
        #pragma unroll
        for (int o = 16; o; o >>= 1) m = fmaxf(m, __shfl_xor_sync(0xffffffffu, m, o));
        if (lid == 0) red[0] = m;
    }
    __syncthreads();
    mx = red[0];
    __syncthreads();

    float4 e;
    e.x = __expf(v.x - mx); e.y = __expf(v.y - mx);
    e.z = __expf(v.z - mx); e.w = __expf(v.w - mx);
    float sum = e.x + e.y + e.z + e.w;
    #pragma unroll
    for (int o = 16; o; o >>= 1) sum += __shfl_xor_sync(0xffffffffu, sum, o);
    if (lid == 0) red[wid] = sum;
    __syncthreads();
    if (t < 32) {
        float s = (lid < 8) ? red[lid] : 0.f;
        #pragma unroll
        for (int o = 16; o; o >>= 1) s += __shfl_xor_sync(0xffffffffu, s, o);
        if (lid == 0) red[0] = s;
    }
    __syncthreads();
    float inv = 1.0f / red[0];
    e.x *= inv; e.y *= inv; e.z *= inv; e.w *= inv;

    bf162 h0, l0, h1, l1;
    split2(e.x, e.y, h0, l0);
    split2(e.z, e.w, h1, l1);
    size_t o = row * (size_t)SEQ + t * 4;
    *reinterpret_cast<bf162*>(Phi + o)     = h0;
    *reinterpret_cast<bf162*>(Phi + o + 2) = h1;
    *reinterpret_cast<bf162*>(Plo + o)     = l0;
    *reinterpret_cast<bf162*>(Plo + o + 2) = l1;
}

// ============================ launch ============================
extern "C" void kernel_launch(void* const* d_in, const int* in_sizes, int n_in,
                              void* d_out, int out_size) {
    const float* x     = (const float*)d_in[0];
    const float* sizei = (const float*)d_in[1];
    const float* amask = (const float*)d_in[2];
    const float* query = (const float*)d_in[3];
    const float* ln_q_w = (const float*)d_in[4];
    const float* ln_q_b = (const float*)d_in[5];
    const float* ln_k_w = (const float*)d_in[6];
    const float* ln_k_b = (const float*)d_in[7];
    const float* Wq = (const float*)d_in[8];
    const float* Wk = (const float*)d_in[9];
    const float* Wv = (const float*)d_in[10];
    const float* bq = (const float*)d_in[11];
    const float* bk = (const float*)d_in[12];
    const float* bv = (const float*)d_in[13];
    const float* Wo = (const float*)d_in[14];
    const float* bo = (const float*)d_in[15];
    float* out = (float*)d_out;

    bf16 *xhi, *xlo, *wkhi, *wklo, *wvhi, *wvlo, *wohi, *wolo;
    bf16 *khhi, *khlo, *vhhi, *vhlo, *qhhi, *qhlo, *phi, *plo, *aohi, *aolo;
    float *qln, *qh, *bias, *scores;
    cudaGetSymbolAddress((void**)&xhi, g_xhi);
    cudaGetSymbolAddress((void**)&xlo, g_xlo);
    cudaGetSymbolAddress((void**)&wkhi, g_wkhi);
    cudaGetSymbolAddress((void**)&wklo, g_wklo);
    cudaGetSymbolAddress((void**)&wvhi, g_wvhi);
    cudaGetSymbolAddress((void**)&wvlo, g_wvlo);
    cudaGetSymbolAddress((void**)&wohi, g_wohi);
    cudaGetSymbolAddress((void**)&wolo, g_wolo);
    cudaGetSymbolAddress((void**)&khhi, g_khhi);
    cudaGetSymbolAddress((void**)&khlo, g_khlo);
    cudaGetSymbolAddress((void**)&vhhi, g_vhhi);
    cudaGetSymbolAddress((void**)&vhlo, g_vhlo);
    cudaGetSymbolAddress((void**)&qhhi, g_qhhi);
    cudaGetSymbolAddress((void**)&qhlo, g_qhlo);
    cudaGetSymbolAddress((void**)&phi, g_phi);
    cudaGetSymbolAddress((void**)&plo, g_plo);
    cudaGetSymbolAddress((void**)&aohi, g_aohi);
    cudaGetSymbolAddress((void**)&aolo, g_aolo);
    cudaGetSymbolAddress((void**)&qln, g_qln);
    cudaGetSymbolAddress((void**)&qh, g_qh);
    cudaGetSymbolAddress((void**)&bias, g_bias);
    cudaGetSymbolAddress((void**)&scores, g_scores);

    cudaFuncSetAttribute(kv_gemm,     cudaFuncAttributeMaxDynamicSharedMemorySize, G3_SMEM);
    cudaFuncSetAttribute(oproj_gemm,  cudaFuncAttributeMaxDynamicSharedMemorySize, G3_SMEM);
    cudaFuncSetAttribute(scores_gemm, cudaFuncAttributeMaxDynamicSharedMemorySize, G3_SMEM);
    cudaFuncSetAttribute(av_gemm,     cudaFuncAttributeMaxDynamicSharedMemorySize, AV_SMEM);

    const float scale = 0.10206207261596575f;  // 1/sqrt(96)

    // 1) LN
    ln_split_kernel<<<MROWS, 256>>>(x, ln_k_w, ln_k_b, xhi, xlo, CTXD);
    ln_kernel<<<NQ, 256>>>(query, ln_q_w, ln_q_b, qln, DMODEL);

    // 2) weight splits
    split_kernel<<<(DMODEL * CTXD + 255) / 256, 256>>>(Wk, wkhi, wklo, DMODEL * CTXD);
    split_kernel<<<(DMODEL * CTXD + 255) / 256, 256>>>(Wv, wvhi, wvlo, DMODEL * CTXD);
    split_kernel<<<(DMODEL * DMODEL + 255) / 256, 256>>>(Wo, wohi, wolo, DMODEL * DMODEL);

    // 3) additive bias
    bias_kernel<<<(MROWS + 255) / 256, 256>>>(sizei, amask, bias, MROWS);

    // 4) K/V projections -> split bf16 outputs
    {
        dim3 grid(DMODEL / 128, MROWS / 128);
        kv_gemm<<<grid, 256, G3_SMEM>>>(xhi, xlo, wkhi, wklo, bk, khhi, khlo);
        kv_gemm<<<grid, 256, G3_SMEM>>>(xhi, xlo, wvhi, wvlo, bv, vhhi, vhlo);
    }

    // 5) Q projection (SIMT) -> split
    gemm_nt_kernel<<<dim3(DMODEL / TBN, NQ / TBM), 256>>>(
        qln, DMODEL, Wq, DMODEL, qh, DMODEL, NQ, DMODEL, DMODEL, 1.0f, bq);
    split_kernel<<<(NQ * DMODEL + 255) / 256, 256>>>(qh, qhhi, qhlo, NQ * DMODEL);

    // 6) scores (tensor) + bias
    scores_gemm<<<dim3(SEQ / 128, NQ / 128, NZ), 256, G3_SMEM>>>(
        qhhi, qhlo, khhi, khlo, bias, scores, scale);

    // 7) softmax -> split bf16 P
    softmax_split_kernel<<<NZ * NQ, 256>>>(scores, phi, plo);

    // 8) attn @ V (tensor) -> split bf16 attnout
    av_gemm<<<dim3(NQ / 128, NZ), 256, AV_SMEM>>>(phi, plo, vhhi, vhlo, aohi, aolo);

    // 9) output projection (tensor)
    oproj_gemm<<<dim3(DMODEL / 128, BATCH * NQ / 128), 256, G3_SMEM>>>(
        aohi, aolo, wohi, wolo, bo, out);
}

// round 5
// speedup vs baseline: 2.7600x; 1.1058x over previous
#include <cuda_runtime.h>
#include <cuda_bf16.h>
#include <cstdint>

#define BATCH     32
#define SEQ       1024
#define CTXD      1024
#define DMODEL    768
#define NHEAD     8
#define HDIM      96
#define NQ        256
#define MROWS     (BATCH * SEQ)   // 32768
#define NZ        (BATCH * NHEAD) // 256

typedef __nv_bfloat16 bf16;
typedef __nv_bfloat162 bf162;

// ============================ device scratch ============================
__device__ bf16 g_xhi[MROWS * CTXD];
__device__ bf16 g_xlo[MROWS * CTXD];
__device__ bf16 g_wkhi[DMODEL * CTXD];
__device__ bf16 g_wklo[DMODEL * CTXD];
__device__ bf16 g_wvhi[DMODEL * CTXD];
__device__ bf16 g_wvlo[DMODEL * CTXD];
__device__ bf16 g_wohi[DMODEL * DMODEL];
__device__ bf16 g_wolo[DMODEL * DMODEL];
__device__ bf16 g_khhi[MROWS * DMODEL];
__device__ bf16 g_khlo[MROWS * DMODEL];
__device__ bf16 g_vhhi[MROWS * DMODEL];
__device__ bf16 g_vhlo[MROWS * DMODEL];
__device__ bf16 g_qhhi[NQ * DMODEL];
__device__ bf16 g_qhlo[NQ * DMODEL];
__device__ bf16 g_aohi[BATCH * NQ * DMODEL];
__device__ bf16 g_aolo[BATCH * NQ * DMODEL];
__device__ float g_qln[NQ * DMODEL];
__device__ float g_qh[NQ * DMODEL];
__device__ float g_bias[MROWS];

// ============================ asm helpers ============================
__device__ __forceinline__ uint32_t smem_u32(const void* p) {
    uint32_t a;
    asm("{ .reg .u64 t; cvta.to.shared.u64 t, %1; cvt.u32.u64 %0, t; }" : "=r"(a) : "l"(p));
    return a;
}
__device__ __forceinline__ void ldm_x4(uint32_t* r, uint32_t addr) {
    asm volatile("ldmatrix.sync.aligned.m8n8.x4.shared.b16 {%0,%1,%2,%3}, [%4];"
                 : "=r"(r[0]), "=r"(r[1]), "=r"(r[2]), "=r"(r[3]) : "r"(addr));
}
__device__ __forceinline__ void ldm_x4_t(uint32_t* r, uint32_t addr) {
    asm volatile("ldmatrix.sync.aligned.m8n8.x4.trans.shared.b16 {%0,%1,%2,%3}, [%4];"
                 : "=r"(r[0]), "=r"(r[1]), "=r"(r[2]), "=r"(r[3]) : "r"(addr));
}
__device__ __forceinline__ void mma16816(float* c, const uint32_t* a, const uint32_t* b) {
    asm volatile("mma.sync.aligned.m16n8k16.row.col.f32.bf16.bf16.f32 "
                 "{%0,%1,%2,%3}, {%4,%5,%6,%7}, {%8,%9}, {%0,%1,%2,%3};"
                 : "+f"(c[0]), "+f"(c[1]), "+f"(c[2]), "+f"(c[3])
                 : "r"(a[0]), "r"(a[1]), "r"(a[2]), "r"(a[3]), "r"(b[0]), "r"(b[1]));
}
__device__ __forceinline__ void cp16(uint32_t dst, const void* src) {
    asm volatile("cp.async.cg.shared.global [%0], [%1], 16;" :: "r"(dst), "l"(src));
}
#define CP_COMMIT() asm volatile("cp.async.commit_group;")
#define CP_WAIT0()  asm volatile("cp.async.wait_group 0;")

__device__ __forceinline__ void split2(float v0, float v1, bf162& h2, bf162& l2) {
    bf16 h0 = __float2bfloat16(v0);
    bf16 h1 = __float2bfloat16(v1);
    h2 = bf162(h0, h1);
    l2 = bf162(__float2bfloat16(v0 - __bfloat162float(h0)),
               __float2bfloat16(v1 - __bfloat162float(h1)));
}
__device__ __forceinline__ void splitpack(float v0, float v1, uint32_t& hi, uint32_t& lo) {
    bf162 h2, l2;
    split2(v0, v1, h2, l2);
    hi = *reinterpret_cast<uint32_t*>(&h2);
    lo = *reinterpret_cast<uint32_t*>(&l2);
}

// ============================ generalized split-bf16 NT GEMM ============================
#define G3_SMEM 81920
#define LDS_BF 40

template<int EPI>  // 0: fp32 out, 1: split bf16 out
__device__ __forceinline__ void gemm3_dev(
    char* smem,
    const bf16* __restrict__ Ahi, const bf16* __restrict__ Alo, int lda,
    const bf16* __restrict__ Bhi, const bf16* __restrict__ Blo, int ldb,
    int K, int m0, int n0, float alpha, const float* __restrict__ bias_n,
    float* __restrict__ Cf, bf16* __restrict__ Chi, bf16* __restrict__ Clo, int ldc)
{
    const int tid  = threadIdx.x;
    const int wid  = tid >> 5;
    const int lane = tid & 31;
    const int wm = (wid & 3) * 32;
    const int wn = (wid >> 2) * 64;

    const uint32_t smBase = smem_u32(smem);
    const uint32_t aRow = (uint32_t)(wm + (lane & 15)) * LDS_BF + (uint32_t)(lane >> 4) * 8u;
    const uint32_t bRow = (uint32_t)(wn + (lane & 7) + ((lane >> 4) * 8)) * LDS_BF
                        + (uint32_t)((lane >> 3) & 1) * 8u;

    float acc[2][8][4];
    #pragma unroll
    for (int i = 0; i < 2; i++)
        #pragma unroll
        for (int j = 0; j < 8; j++)
            #pragma unroll
            for (int k = 0; k < 4; k++) acc[i][j][k] = 0.f;

    const int r  = tid >> 2;
    const int cc = tid & 3;
    const int nchunks = K >> 5;

    auto load_chunk = [&](int k0, int buf) {
        uint32_t aB = smBase + (uint32_t)buf * 20480u;
        uint32_t bB = smBase + 40960u + (uint32_t)buf * 20480u;
        #pragma unroll
        for (int h = 0; h < 2; h++) {
            int rr = r + h * 64;
            uint32_t so = ((uint32_t)rr * LDS_BF + (uint32_t)cc * 8u) * 2u;
            size_t ga = (size_t)(m0 + rr) * lda + k0 + cc * 8;
            size_t gb = (size_t)(n0 + rr) * ldb + k0 + cc * 8;
            cp16(aB + so,           Ahi + ga);
            cp16(aB + 10240u + so,  Alo + ga);
            cp16(bB + so,           Bhi + gb);
            cp16(bB + 10240u + so,  Blo + gb);
        }
    };

    load_chunk(0, 0);
    CP_COMMIT();

    for (int c = 0; c < nchunks; c++) {
        CP_WAIT0();
        __syncthreads();
        if (c + 1 < nchunks) { load_chunk((c + 1) << 5, (c + 1) & 1); CP_COMMIT(); }

        uint32_t aB = smBase + (uint32_t)(c & 1) * 20480u;
        uint32_t bB = smBase + 40960u + (uint32_t)(c & 1) * 20480u;
        #pragma unroll
        for (int ks = 0; ks < 2; ks++) {
            const uint32_t kcol = (uint32_t)ks * 16u;
            uint32_t ahi[2][4], alo[2][4], b[4][4];
            #pragma unroll
            for (int mi = 0; mi < 2; mi++) {
                uint32_t off = (aRow + (uint32_t)mi * 16u * LDS_BF + kcol) * 2u;
                ldm_x4(ahi[mi], aB + off);
                ldm_x4(alo[mi], aB + 10240u + off);
            }
            #pragma unroll
            for (int g = 0; g < 4; g++) {
                uint32_t off = (bRow + (uint32_t)g * 16u * LDS_BF + kcol) * 2u;
                ldm_x4(b[g], bB + off);
            }
            #pragma unroll
            for (int mi = 0; mi < 2; mi++)
                #pragma unroll
                for (int nj = 0; nj < 8; nj++) {
                    const uint32_t* bf = &b[nj >> 1][(nj & 1) * 2];
                    mma16816(acc[mi][nj], ahi[mi], bf);
                    mma16816(acc[mi][nj], alo[mi], bf);
                }
            #pragma unroll
            for (int g = 0; g < 4; g++) {
                uint32_t off = (bRow + (uint32_t)g * 16u * LDS_BF + kcol) * 2u;
                ldm_x4(b[g], bB + 10240u + off);
            }
            #pragma unroll
            for (int mi = 0; mi < 2; mi++)
                #pragma unroll
                for (int nj = 0; nj < 8; nj++)
                    mma16816(acc[mi][nj], ahi[mi], &b[nj >> 1][(nj & 1) * 2]);
        }
        __syncthreads();
    }

    #pragma unroll
    for (int mi = 0; mi < 2; mi++) {
        int gm = m0 + wm + mi * 16 + (lane >> 2);
        #pragma unroll
        for (int nj = 0; nj < 8; nj++) {
            int gn = n0 + wn + nj * 8 + (lane & 3) * 2;
            float b0 = bias_n ? bias_n[gn]     : 0.f;
            float b1 = bias_n ? bias_n[gn + 1] : 0.f;
            float v00 = alpha * acc[mi][nj][0] + b0;
            float v01 = alpha * acc[mi][nj][1] + b1;
            float v10 = alpha * acc[mi][nj][2] + b0;
            float v11 = alpha * acc[mi][nj][3] + b1;
            if (EPI == 0) {
                *reinterpret_cast<float2*>(Cf + (size_t)gm * ldc + gn)       = make_float2(v00, v01);
                *reinterpret_cast<float2*>(Cf + (size_t)(gm + 8) * ldc + gn) = make_float2(v10, v11);
            } else {
                bf162 h2, l2;
                split2(v00, v01, h2, l2);
                *reinterpret_cast<bf162*>(Chi + (size_t)gm * ldc + gn) = h2;
                *reinterpret_cast<bf162*>(Clo + (size_t)gm * ldc + gn) = l2;
                split2(v10, v11, h2, l2);
                *reinterpret_cast<bf162*>(Chi + (size_t)(gm + 8) * ldc + gn) = h2;
                *reinterpret_cast<bf162*>(Clo + (size_t)(gm + 8) * ldc + gn) = l2;
            }
        }
    }
}

__global__ void __launch_bounds__(256, 1)
kv_gemm(const bf16* __restrict__ Ahi, const bf16* __restrict__ Alo,
        const bf16* __restrict__ Bhi, const bf16* __restrict__ Blo,
        const float* __restrict__ bias_n, bf16* __restrict__ Chi, bf16* __restrict__ Clo) {
    extern __shared__ char smem[];
    gemm3_dev<1>(smem, Ahi, Alo, CTXD, Bhi, Blo, CTXD, CTXD,
                 blockIdx.y * 128, blockIdx.x * 128, 1.0f, bias_n,
                 nullptr, Chi, Clo, DMODEL);
}

__global__ void __launch_bounds__(256, 1)
oproj_gemm(const bf16* __restrict__ Ahi, const bf16* __restrict__ Alo,
           const bf16* __restrict__ Bhi, const bf16* __restrict__ Blo,
           const float* __restrict__ bias_n, float* __restrict__ C) {
    extern __shared__ char smem[];
    gemm3_dev<0>(smem, Ahi, Alo, DMODEL, Bhi, Blo, DMODEL, DMODEL,
                 blockIdx.y * 128, blockIdx.x * 128, 1.0f, bias_n,
                 C, nullptr, nullptr, DMODEL);
}

// ============================ fused flash attention ============================
// Per CTA: z = blockIdx.y (b,h), q-tile 128 = blockIdx.x. Loop L in chunks of 64.
// S = scale*(Q@K^T) + bias[b,l]; online softmax; O += P@V; epilogue O/l -> split bf16.
// smem (bytes): Q hi/lo @0 (2x26624); K @53248 (2 bufs x (hi13312+lo13312));
//               V @106496 (same); bias @159744 (2 x 256).
#define FA_SMEM 160256
#define FA_LDS 104

__global__ void __launch_bounds__(256, 1)
fa_kernel(const bf16* __restrict__ Qhi, const bf16* __restrict__ Qlo,
          const bf16* __restrict__ Khi, const bf16* __restrict__ Klo,
          const bf16* __restrict__ Vhi, const bf16* __restrict__ Vlo,
          const float* __restrict__ biasBL, float scale,
          bf16* __restrict__ Ohi, bf16* __restrict__ Olo) {
    extern __shared__ char smem[];
    const int tid = threadIdx.x;
    const int wid = tid >> 5, lane = tid & 31;
    const int z = blockIdx.y;
    const int b = z >> 3, h = z & 7;
    const int q0 = blockIdx.x * 128;
    const size_t bSeq = (size_t)b * SEQ;
    const int hOff = h * HDIM;

    const uint32_t smBase = smem_u32(smem);
    const uint32_t KBASE = 53248u, VBASE = 106496u, TSTR = 13312u, BBASE = 159744u;

    // ---- load Q (once) ----
    for (int i = tid; i < 1536; i += 256) {
        int row = i / 12, col = i % 12;
        uint32_t so = ((uint32_t)row * FA_LDS + (uint32_t)col * 8u) * 2u;
        size_t go = (size_t)(q0 + row) * DMODEL + hOff + col * 8;
        cp16(smBase + so,           Qhi + go);
        cp16(smBase + 26624u + so,  Qlo + go);
    }
    CP_COMMIT();

    auto load_kv = [&](int c, int buf) {
        int l0 = c * 64;
        uint32_t kB = smBase + KBASE + (uint32_t)buf * 26624u;
        uint32_t vB = smBase + VBASE + (uint32_t)buf * 26624u;
        for (int i = tid; i < 768; i += 256) {
            int row = i / 12, col = i % 12;
            uint32_t so = ((uint32_t)row * FA_LDS + (uint32_t)col * 8u) * 2u;
            size_t go = (bSeq + l0 + row) * DMODEL + hOff + col * 8;
            cp16(kB + so,        Khi + go);
            cp16(kB + TSTR + so, Klo + go);
            cp16(vB + so,        Vhi + go);
            cp16(vB + TSTR + so, Vlo + go);
        }
        if (tid < 16)
            cp16(smBase + BBASE + (uint32_t)buf * 256u + (uint32_t)tid * 16u,
                 biasBL + bSeq + l0 + tid * 4);
    };
    load_kv(0, 0);
    CP_COMMIT();

    // fragment addressing
    const uint32_t aRow = (uint32_t)(wid * 16 + (lane & 15)) * FA_LDS + (uint32_t)(lane >> 4) * 8u;
    const uint32_t bRow = (uint32_t)((lane & 7) + ((lane >> 4) * 8)) * FA_LDS
                        + (uint32_t)((lane >> 3) & 1) * 8u;
    const uint32_t vLaneRow = (uint32_t)((lane & 7) + ((lane >> 3) & 1) * 8);
    const uint32_t vLaneCol = (uint32_t)(lane >> 4) * 8u;

    float oacc[12][4];
    #pragma unroll
    for (int j = 0; j < 12; j++)
        #pragma unroll
        for (int k = 0; k < 4; k++) oacc[j][k] = 0.f;
    float m0 = -1e30f, m1 = -1e30f, l0s = 0.f, l1s = 0.f;

    for (int c = 0; c < 16; c++) {
        CP_WAIT0();
        __syncthreads();
        if (c + 1 < 16) { load_kv(c + 1, (c + 1) & 1); CP_COMMIT(); }

        const uint32_t kB = smBase + KBASE + (uint32_t)(c & 1) * 26624u;
        const uint32_t vB = smBase + VBASE + (uint32_t)(c & 1) * 26624u;
        const float* sbias = reinterpret_cast<const float*>(smem + BBASE + (c & 1) * 256);

        // ---- S = Q @ K^T (3-term split) ----
        float s[8][4];
        #pragma unroll
        for (int j = 0; j < 8; j++)
            #pragma unroll
            for (int k = 0; k < 4; k++) s[j][k] = 0.f;

        #pragma unroll
        for (int ks = 0; ks < 6; ks++) {
            const uint32_t kcol = (uint32_t)ks * 16u;
            uint32_t qhiF[4], qloF[4], kk[4];
            uint32_t qoff = (aRow + kcol) * 2u;
            ldm_x4(qhiF, smBase + qoff);
            ldm_x4(qloF, smBase + 26624u + qoff);
            #pragma unroll
            for (int g = 0; g < 4; g++) {
                uint32_t off = (bRow + (uint32_t)g * 16u * FA_LDS + kcol) * 2u;
                ldm_x4(kk, kB + off);
                mma16816(s[2 * g],     qhiF, &kk[0]);
                mma16816(s[2 * g + 1], qhiF, &kk[2]);
                mma16816(s[2 * g],     qloF, &kk[0]);
                mma16816(s[2 * g + 1], qloF, &kk[2]);
                ldm_x4(kk, kB + TSTR + off);
                mma16816(s[2 * g],     qhiF, &kk[0]);
                mma16816(s[2 * g + 1], qhiF, &kk[2]);
            }
        }

        // ---- scale + bias, online softmax ----
        float mx0 = -1e30f, mx1 = -1e30f;
        #pragma unroll
        for (int nj = 0; nj < 8; nj++) {
            int cidx = nj * 8 + (lane & 3) * 2;
            float bj0 = sbias[cidx], bj1 = sbias[cidx + 1];
            s[nj][0] = s[nj][0] * scale + bj0;
            s[nj][1] = s[nj][1] * scale + bj1;
            s[nj][2] = s[nj][2] * scale + bj0;
            s[nj][3] = s[nj][3] * scale + bj1;
            mx0 = fmaxf(mx0, fmaxf(s[nj][0], s[nj][1]));
            mx1 = fmaxf(mx1, fmaxf(s[nj][2], s[nj][3]));
        }
        #pragma unroll
        for (int o = 1; o <= 2; o <<= 1) {
            mx0 = fmaxf(mx0, __shfl_xor_sync(0xffffffffu, mx0, o));
            mx1 = fmaxf(mx1, __shfl_xor_sync(0xffffffffu, mx1, o));
        }
        float mn0 = fmaxf(m0, mx0), mn1 = fmaxf(m1, mx1);
        float cor0 = __expf(m0 - mn0), cor1 = __expf(m1 - mn1);
        l0s *= cor0; l1s *= cor1;
        #pragma unroll
        for (int j = 0; j < 12; j++) {
            oacc[j][0] *= cor0; oacc[j][1] *= cor0;
            oacc[j][2] *= cor1; oacc[j][3] *= cor1;
        }
        m0 = mn0; m1 = mn1;

        float rs0 = 0.f, rs1 = 0.f;
        uint32_t phiF[4][4], ploF[4][4];
        #pragma unroll
        for (int t = 0; t < 4; t++) {
            float p00 = __expf(s[2 * t][0] - mn0);
            float p01 = __expf(s[2 * t][1] - mn0);
            float p10 = __expf(s[2 * t][2] - mn1);
            float p11 = __expf(s[2 * t][3] - mn1);
            float p20 = __expf(s[2 * t + 1][0] - mn0);
            float p21 = __expf(s[2 * t + 1][1] - mn0);
            float p30 = __expf(s[2 * t + 1][2] - mn1);
            float p31 = __expf(s[2 * t + 1][3] - mn1);
            rs0 += p00 + p01 + p20 + p21;
            rs1 += p10 + p11 + p30 + p31;
            splitpack(p00, p01, phiF[t][0], ploF[t][0]);
            splitpack(p10, p11, phiF[t][1], ploF[t][1]);
            splitpack(p20, p21, phiF[t][2], ploF[t][2]);
            splitpack(p30, p31, phiF[t][3], ploF[t][3]);
        }
        #pragma unroll
        for (int o = 1; o <= 2; o <<= 1) {
            rs0 += __shfl_xor_sync(0xffffffffu, rs0, o);
            rs1 += __shfl_xor_sync(0xffffffffu, rs1, o);
        }
        l0s += rs0; l1s += rs1;

        // ---- O += P @ V (3-term split) ----
        #pragma unroll
        for (int t = 0; t < 4; t++) {
            uint32_t vv[4];
            #pragma unroll
            for (int g = 0; g < 6; g++) {
                uint32_t off = (((uint32_t)t * 16u + vLaneRow) * FA_LDS
                                + (uint32_t)g * 16u + vLaneCol) * 2u;
                ldm_x4_t(vv, vB + off);
                mma16816(oacc[2 * g],     phiF[t], &vv[0]);
                mma16816(oacc[2 * g + 1], phiF[t], &vv[2]);
                mma16816(oacc[2 * g],     ploF[t], &vv[0]);
                mma16816(oacc[2 * g + 1], ploF[t], &vv[2]);
                ldm_x4_t(vv, vB + TSTR + off);
                mma16816(oacc[2 * g],     phiF[t], &vv[0]);
                mma16816(oacc[2 * g + 1], phiF[t], &vv[2]);
            }
        }
    }

    // ---- epilogue: O / l, write split bf16 at [(b*256+q), h*96+n] ----
    float inv0 = 1.0f / l0s, inv1 = 1.0f / l1s;
    const int q = q0 + wid * 16 + (lane >> 2);
    #pragma unroll
    for (int j = 0; j < 12; j++) {
        int n = j * 8 + (lane & 3) * 2;
        size_t o0 = ((size_t)(b * NQ + q)) * DMODEL + hOff + n;
        size_t o1 = o0 + (size_t)8 * DMODEL;
        bf162 h2, l2;
        split2(oacc[j][0] * inv0, oacc[j][1] * inv0, h2, l2);
        *reinterpret_cast<bf162*>(Ohi + o0) = h2;
        *reinterpret_cast<bf162*>(Olo + o0) = l2;
        split2(oacc[j][2] * inv1, oacc[j][3] * inv1, h2, l2);
        *reinterpret_cast<bf162*>(Ohi + o1) = h2;
        *reinterpret_cast<bf162*>(Olo + o1) = l2;
    }
}

// ============================ LayerNorm / misc ============================
__device__ __forceinline__ void ln_stats(const float* __restrict__ xr, int ncols,
                                         float& mu, float& rs, float* s1, float* s2) {
    float sum = 0.f, sumsq = 0.f;
    for (int i = threadIdx.x; i < ncols; i += blockDim.x) {
        float v = xr[i];
        sum += v; sumsq += v * v;
    }
    #pragma unroll
    for (int o = 16; o; o >>= 1) {
        sum   += __shfl_xor_sync(0xffffffffu, sum, o);
        sumsq += __shfl_xor_sync(0xffffffffu, sumsq, o);
    }
    int wid = threadIdx.x >> 5, lid = threadIdx.x & 31;
    if (lid == 0) { s1[wid] = sum; s2[wid] = sumsq; }
    __syncthreads();
    if (threadIdx.x < 32) {
        int nw = blockDim.x >> 5;
        float a = (lid < nw) ? s1[lid] : 0.f;
        float c = (lid < nw) ? s2[lid] : 0.f;
        #pragma unroll
        for (int o = 16; o; o >>= 1) {
            a += __shfl_xor_sync(0xffffffffu, a, o);
            c += __shfl_xor_sync(0xffffffffu, c, o);
        }
        if (lid == 0) { s1[0] = a; s2[0] = c; }
    }
    __syncthreads();
    float inv_n = 1.0f / (float)ncols;
    mu = s1[0] * inv_n;
    float var = s2[0] * inv_n - mu * mu;
    rs = rsqrtf(var + 1e-5f);
}

__global__ void ln_kernel(const float* __restrict__ x, const float* __restrict__ w,
                          const float* __restrict__ b, float* __restrict__ out, int ncols) {
    __shared__ float s1[32], s2[32];
    const size_t row = blockIdx.x;
    const float* xr = x + row * (size_t)ncols;
    float mu, rs;
    ln_stats(xr, ncols, mu, rs, s1, s2);
    float* orow = out + row * (size_t)ncols;
    for (int i = threadIdx.x; i < ncols; i += blockDim.x)
        orow[i] = (xr[i] - mu) * rs * w[i] + b[i];
}

__global__ void ln_split_kernel(const float* __restrict__ x, const float* __restrict__ w,
                                const float* __restrict__ b,
                                bf16* __restrict__ hi, bf16* __restrict__ lo, int ncols) {
    __shared__ float s1[32], s2[32];
    const size_t row = blockIdx.x;
    const float* xr = x + row * (size_t)ncols;
    float mu, rs;
    ln_stats(xr, ncols, mu, rs, s1, s2);
    bf16* hrow = hi + row * (size_t)ncols;
    bf16* lrow = lo + row * (size_t)ncols;
    for (int i = threadIdx.x; i < ncols; i += blockDim.x) {
        float y = (xr[i] - mu) * rs * w[i] + b[i];
        bf16 hh = __float2bfloat16(y);
        hrow[i] = hh;
        lrow[i] = __float2bfloat16(y - __bfloat162float(hh));
    }
}

__global__ void split_kernel(const float* __restrict__ x,
                             bf16* __restrict__ hi, bf16* __restrict__ lo, int n) {
    int i = blockIdx.x * blockDim.x + threadIdx.x;
    if (i < n) {
        float v = x[i];
        bf16 h = __float2bfloat16(v);
        hi[i] = h;
        lo[i] = __float2bfloat16(v - __bfloat162float(h));
    }
}

__global__ void bias_kernel(const float* __restrict__ size_in, const float* __restrict__ mask,
                            float* __restrict__ bias, int n) {
    int i = blockIdx.x * blockDim.x + threadIdx.x;
    if (i < n) {
        float s = size_in[i];
        s = (s < 0.5f) ? 1.0f : s;
        bias[i] = logf(s) + mask[i];
    }
}

// ============================ SIMT GEMM (Q-proj only) ============================
#define TBM 64
#define TBN 64
#define TBK 16
#define SPAD 4

__global__ void __launch_bounds__(256)
gemm_nt_kernel(const float* __restrict__ A, int lda,
               const float* __restrict__ B, int ldb,
               float* __restrict__ C, int ldc,
               int M, int N, int K, float alpha, const float* __restrict__ bias_n) {
    __shared__ __align__(16) float As[TBK][TBM + SPAD];
    __shared__ __align__(16) float Bs[TBK][TBN + SPAD];
    const int m0 = blockIdx.y * TBM;
    const int n0 = blockIdx.x * TBN;
    const int t  = threadIdx.x;
    const int tx = t & 15, ty = t >> 4;
    float acc[4][4] = {};
    for (int k0 = 0; k0 < K; k0 += TBK) {
        {
            int col = t & 15, rowb = t >> 4;
            #pragma unroll
            for (int i = 0; i < 4; i++) {
                int rr = rowb + i * 16;
                As[col][rr] = A[(size_t)(m0 + rr) * lda + k0 + col];
            }
        }
        {
            int col = t & 15, rowb = t >> 4;
            #pragma unroll
            for (int i = 0; i < 4; i++) {
                int nn = rowb + i * 16;
                Bs[col][nn] = B[(size_t)(n0 + nn) * ldb + k0 + col];
            }
        }
        __syncthreads();
        #pragma unroll
        for (int kk = 0; kk < TBK; kk++) {
            float4 av = *reinterpret_cast<const float4*>(&As[kk][ty * 4]);
            float4 bv = *reinterpret_cast<const float4*>(&Bs[kk][tx * 4]);
            float a[4] = {av.x, av.y, av.z, av.w};
            float b[4] = {bv.x, bv.y, bv.z, bv.w};
            #pragma unroll
            for (int i = 0; i < 4; i++)
                #pragma unroll
                for (int j = 0; j < 4; j++)
                    acc[i][j] += a[i] * b[j];
        }
        __syncthreads();
    }
    #pragma unroll
    for (int i = 0; i < 4; i++) {
        int gm = m0 + ty * 4 + i;
        #pragma unroll
        for (int j = 0; j < 4; j++) {
            int gn = n0 + tx * 4 + j;
            float v = alpha * acc[i][j];
            if (bias_n) v += bias_n[gn];
            C[(size_t)gm * ldc + gn] = v;
        }
    }
}

// ============================ launch ============================
extern "C" void kernel_launch(void* const* d_in, const int* in_sizes, int n_in,
                              void* d_out, int out_size) {
    const float* x     = (const float*)d_in[0];
    const float* sizei = (const float*)d_in[1];
    const float* amask = (const float*)d_in[2];
    const float* query = (const float*)d_in[3];
    const float* ln_q_w = (const float*)d_in[4];
    const float* ln_q_b = (const float*)d_in[5];
    const float* ln_k_w = (const float*)d_in[6];
    const float* ln_k_b = (const float*)d_in[7];
    const float* Wq = (const float*)d_in[8];
    const float* Wk = (const float*)d_in[9];
    const float* Wv = (const float*)d_in[10];
    const float* bq = (const float*)d_in[11];
    const float* bk = (const float*)d_in[12];
    const float* bv = (const float*)d_in[13];
    const float* Wo = (const float*)d_in[14];
    const float* bo = (const float*)d_in[15];
    float* out = (float*)d_out;

    bf16 *xhi, *xlo, *wkhi, *wklo, *wvhi, *wvlo, *wohi, *wolo;
    bf16 *khhi, *khlo, *vhhi, *vhlo, *qhhi, *qhlo, *aohi, *aolo;
    float *qln, *qh, *bias;
    cudaGetSymbolAddress((void**)&xhi, g_xhi);
    cudaGetSymbolAddress((void**)&xlo, g_xlo);
    cudaGetSymbolAddress((void**)&wkhi, g_wkhi);
    cudaGetSymbolAddress((void**)&wklo, g_wklo);
    cudaGetSymbolAddress((void**)&wvhi, g_wvhi);
    cudaGetSymbolAddress((void**)&wvlo, g_wvlo);
    cudaGetSymbolAddress((void**)&wohi, g_wohi);
    cudaGetSymbolAddress((void**)&wolo, g_wolo);
    cudaGetSymbolAddress((void**)&khhi, g_khhi);
    cudaGetSymbolAddress((void**)&khlo, g_khlo);
    cudaGetSymbolAddress((void**)&vhhi, g_vhhi);
    cudaGetSymbolAddress((void**)&vhlo, g_vhlo);
    cudaGetSymbolAddress((void**)&qhhi, g_qhhi);
    cudaGetSymbolAddress((void**)&qhlo, g_qhlo);
    cudaGetSymbolAddress((void**)&aohi, g_aohi);
    cudaGetSymbolAddress((void**)&aolo, g_aolo);
    cudaGetSymbolAddress((void**)&qln, g_qln);
    cudaGetSymbolAddress((void**)&qh, g_qh);
    cudaGetSymbolAddress((void**)&bias, g_bias);

    cudaFuncSetAttribute(kv_gemm,    cudaFuncAttributeMaxDynamicSharedMemorySize, G3_SMEM);
    cudaFuncSetAttribute(oproj_gemm, cudaFuncAttributeMaxDynamicSharedMemorySize, G3_SMEM);
    cudaFuncSetAttribute(fa_kernel,  cudaFuncAttributeMaxDynamicSharedMemorySize, FA_SMEM);

    const float scale = 0.10206207261596575f;  // 1/sqrt(96)

    // launch order chosen so index 3 (the ncu-profiled launch) = kv_gemm(K)
    ln_split_kernel<<<MROWS, 256>>>(x, ln_k_w, ln_k_b, xhi, xlo, CTXD);               // 0
    split_kernel<<<(DMODEL * CTXD + 255) / 256, 256>>>(Wk, wkhi, wklo, DMODEL * CTXD); // 1
    split_kernel<<<(DMODEL * CTXD + 255) / 256, 256>>>(Wv, wvhi, wvlo, DMODEL * CTXD); // 2
    {
        dim3 grid(DMODEL / 128, MROWS / 128);
        kv_gemm<<<grid, 256, G3_SMEM>>>(xhi, xlo, wkhi, wklo, bk, khhi, khlo);         // 3 (profiled)
        kv_gemm<<<grid, 256, G3_SMEM>>>(xhi, xlo, wvhi, wvlo, bv, vhhi, vhlo);         // 4
    }
    ln_kernel<<<NQ, 256>>>(query, ln_q_w, ln_q_b, qln, DMODEL);                        // 5
    split_kernel<<<(DMODEL * DMODEL + 255) / 256, 256>>>(Wo, wohi, wolo, DMODEL * DMODEL); // 6
    bias_kernel<<<(MROWS + 255) / 256, 256>>>(sizei, amask, bias, MROWS);              // 7
    gemm_nt_kernel<<<dim3(DMODEL / TBN, NQ / TBM), 256>>>(                             // 8
        qln, DMODEL, Wq, DMODEL, qh, DMODEL, NQ, DMODEL, DMODEL, 1.0f, bq);
    split_kernel<<<(NQ * DMODEL + 255) / 256, 256>>>(qh, qhhi, qhlo, NQ * DMODEL);     // 9

    // fused scores+softmax+AV                                                          // 10
    fa_kernel<<<dim3(NQ / 128, NZ), 256, FA_SMEM>>>(
        qhhi, qhlo, khhi, khlo, vhhi, vhlo, bias, scale, aohi, aolo);

    // output projection                                                                // 11
    oproj_gemm<<<dim3(DMODEL / 128, BATCH * NQ / 128), 256, G3_SMEM>>>(
        aohi, aolo, wohi, wolo, bo, out);
}

// round 6
// speedup vs baseline: 2.9007x; 1.0509x over previous
#include <cuda_runtime.h>
#include <cuda_bf16.h>
#include <cstdint>

#define BATCH     32
#define SEQ       1024
#define CTXD      1024
#define DMODEL    768
#define NHEAD     8
#define HDIM      96
#define NQ        256
#define MROWS     (BATCH * SEQ)   // 32768
#define NZ        (BATCH * NHEAD) // 256

typedef __nv_bfloat16 bf16;
typedef __nv_bfloat162 bf162;

// ============================ device scratch ============================
__device__ bf16 g_xhi[MROWS * CTXD];
__device__ bf16 g_xlo[MROWS * CTXD];
__device__ bf16 g_wkhi[DMODEL * CTXD];
__device__ bf16 g_wklo[DMODEL * CTXD];
__device__ bf16 g_wvhi[DMODEL * CTXD];
__device__ bf16 g_wvlo[DMODEL * CTXD];
__device__ bf16 g_wohi[DMODEL * DMODEL];
__device__ bf16 g_wolo[DMODEL * DMODEL];
__device__ bf16 g_khhi[MROWS * DMODEL];
__device__ bf16 g_khlo[MROWS * DMODEL];
__device__ bf16 g_vhhi[MROWS * DMODEL];
__device__ bf16 g_vhlo[MROWS * DMODEL];
__device__ bf16 g_qhhi[NQ * DMODEL];
__device__ bf16 g_qhlo[NQ * DMODEL];
__device__ bf16 g_aohi[BATCH * NQ * DMODEL];
__device__ bf16 g_aolo[BATCH * NQ * DMODEL];
__device__ float g_qln[NQ * DMODEL];
__device__ float g_qh[NQ * DMODEL];
__device__ float g_bias[MROWS];

// ============================ asm helpers ============================
__device__ __forceinline__ uint32_t smem_u32(const void* p) {
    uint32_t a;
    asm("{ .reg .u64 t; cvta.to.shared.u64 t, %1; cvt.u32.u64 %0, t; }" : "=r"(a) : "l"(p));
    return a;
}
__device__ __forceinline__ void ldm_x4(uint32_t* r, uint32_t addr) {
    asm volatile("ldmatrix.sync.aligned.m8n8.x4.shared.b16 {%0,%1,%2,%3}, [%4];"
                 : "=r"(r[0]), "=r"(r[1]), "=r"(r[2]), "=r"(r[3]) : "r"(addr));
}
__device__ __forceinline__ void ldm_x4_t(uint32_t* r, uint32_t addr) {
    asm volatile("ldmatrix.sync.aligned.m8n8.x4.trans.shared.b16 {%0,%1,%2,%3}, [%4];"
                 : "=r"(r[0]), "=r"(r[1]), "=r"(r[2]), "=r"(r[3]) : "r"(addr));
}
__device__ __forceinline__ void mma16816(float* c, const uint32_t* a, const uint32_t* b) {
    asm volatile("mma.sync.aligned.m16n8k16.row.col.f32.bf16.bf16.f32 "
                 "{%0,%1,%2,%3}, {%4,%5,%6,%7}, {%8,%9}, {%0,%1,%2,%3};"
                 : "+f"(c[0]), "+f"(c[1]), "+f"(c[2]), "+f"(c[3])
                 : "r"(a[0]), "r"(a[1]), "r"(a[2]), "r"(a[3]), "r"(b[0]), "r"(b[1]));
}
__device__ __forceinline__ void cp16(uint32_t dst, const void* src) {
    asm volatile("cp.async.cg.shared.global [%0], [%1], 16;" :: "r"(dst), "l"(src));
}
#define CP_COMMIT() asm volatile("cp.async.commit_group;")
#define CP_WAIT0()  asm volatile("cp.async.wait_group 0;")

__device__ __forceinline__ void split2(float v0, float v1, bf162& h2, bf162& l2) {
    bf16 h0 = __float2bfloat16(v0);
    bf16 h1 = __float2bfloat16(v1);
    h2 = bf162(h0, h1);
    l2 = bf162(__float2bfloat16(v0 - __bfloat162float(h0)),
               __float2bfloat16(v1 - __bfloat162float(h1)));
}
__device__ __forceinline__ void splitpack(float v0, float v1, uint32_t& hi, uint32_t& lo) {
    bf162 h2, l2;
    split2(v0, v1, h2, l2);
    hi = *reinterpret_cast<uint32_t*>(&h2);
    lo = *reinterpret_cast<uint32_t*>(&l2);
}

// ============================ split-bf16 NT GEMM (2 CTAs/SM) ============================
// K-chunk 16, double-buffered. smem: A: buf*12288 + term*6144 ; B: 24576 + buf*12288 + term*6144
#define G3_SMEM 49152
#define LDS_BF 24      // bf16 row stride (48B, odd 16B-granule count -> conflict-free)
#define TILE_B 6144u   // 128 * 24 * 2

template<int EPI>  // 0: fp32 out, 1: split bf16 out
__device__ __forceinline__ void gemm3_dev(
    char* smem,
    const bf16* __restrict__ Ahi, const bf16* __restrict__ Alo, int lda,
    const bf16* __restrict__ Bhi, const bf16* __restrict__ Blo, int ldb,
    int K, int m0, int n0, float alpha, const float* __restrict__ bias_n,
    float* __restrict__ Cf, bf16* __restrict__ Chi, bf16* __restrict__ Clo, int ldc)
{
    const int tid  = threadIdx.x;
    const int wid  = tid >> 5;
    const int lane = tid & 31;
    const int wm = (wid & 3) * 32;
    const int wn = (wid >> 2) * 64;

    const uint32_t smBase = smem_u32(smem);
    const uint32_t aRow = (uint32_t)(wm + (lane & 15)) * LDS_BF + (uint32_t)(lane >> 4) * 8u;
    const uint32_t bRow = (uint32_t)(wn + (lane & 7) + ((lane >> 4) * 8)) * LDS_BF
                        + (uint32_t)((lane >> 3) & 1) * 8u;

    float acc[2][8][4];
    #pragma unroll
    for (int i = 0; i < 2; i++)
        #pragma unroll
        for (int j = 0; j < 8; j++)
            #pragma unroll
            for (int k = 0; k < 4; k++) acc[i][j][k] = 0.f;

    const int r2 = tid >> 1;     // row 0..127
    const int c2 = tid & 1;      // 16B column 0..1
    const int nchunks = K >> 4;

    auto load_chunk = [&](int k0, int buf) {
        uint32_t aB = smBase + (uint32_t)buf * (2u * TILE_B);
        uint32_t bB = smBase + 4u * TILE_B + (uint32_t)buf * (2u * TILE_B);
        uint32_t so = ((uint32_t)r2 * LDS_BF + (uint32_t)c2 * 8u) * 2u;
        size_t ga = (size_t)(m0 + r2) * lda + k0 + c2 * 8;
        size_t gb = (size_t)(n0 + r2) * ldb + k0 + c2 * 8;
        cp16(aB + so,          Ahi + ga);
        cp16(aB + TILE_B + so, Alo + ga);
        cp16(bB + so,          Bhi + gb);
        cp16(bB + TILE_B + so, Blo + gb);
    };

    load_chunk(0, 0);
    CP_COMMIT();

    for (int c = 0; c < nchunks; c++) {
        CP_WAIT0();
        __syncthreads();
        if (c + 1 < nchunks) { load_chunk((c + 1) << 4, (c + 1) & 1); CP_COMMIT(); }

        uint32_t aB = smBase + (uint32_t)(c & 1) * (2u * TILE_B);
        uint32_t bB = smBase + 4u * TILE_B + (uint32_t)(c & 1) * (2u * TILE_B);
        uint32_t ahi[2][4], alo[2][4], b[4][4];
        #pragma unroll
        for (int mi = 0; mi < 2; mi++) {
            uint32_t off = (aRow + (uint32_t)mi * 16u * LDS_BF) * 2u;
            ldm_x4(ahi[mi], aB + off);
            ldm_x4(alo[mi], aB + TILE_B + off);
        }
        #pragma unroll
        for (int g = 0; g < 4; g++) {
            uint32_t off = (bRow + (uint32_t)g * 16u * LDS_BF) * 2u;
            ldm_x4(b[g], bB + off);
        }
        #pragma unroll
        for (int mi = 0; mi < 2; mi++)
            #pragma unroll
            for (int nj = 0; nj < 8; nj++) {
                const uint32_t* bf = &b[nj >> 1][(nj & 1) * 2];
                mma16816(acc[mi][nj], ahi[mi], bf);
                mma16816(acc[mi][nj], alo[mi], bf);
            }
        #pragma unroll
        for (int g = 0; g < 4; g++) {
            uint32_t off = (bRow + (uint32_t)g * 16u * LDS_BF) * 2u;
            ldm_x4(b[g], bB + TILE_B + off);
        }
        #pragma unroll
        for (int mi = 0; mi < 2; mi++)
            #pragma unroll
            for (int nj = 0; nj < 8; nj++)
                mma16816(acc[mi][nj], ahi[mi], &b[nj >> 1][(nj & 1) * 2]);
        __syncthreads();
    }

    #pragma unroll
    for (int mi = 0; mi < 2; mi++) {
        int gm = m0 + wm + mi * 16 + (lane >> 2);
        #pragma unroll
        for (int nj = 0; nj < 8; nj++) {
            int gn = n0 + wn + nj * 8 + (lane & 3) * 2;
            float b0 = bias_n ? bias_n[gn]     : 0.f;
            float b1 = bias_n ? bias_n[gn + 1] : 0.f;
            float v00 = alpha * acc[mi][nj][0] + b0;
            float v01 = alpha * acc[mi][nj][1] + b1;
            float v10 = alpha * acc[mi][nj][2] + b0;
            float v11 = alpha * acc[mi][nj][3] + b1;
            if (EPI == 0) {
                *reinterpret_cast<float2*>(Cf + (size_t)gm * ldc + gn)       = make_float2(v00, v01);
                *reinterpret_cast<float2*>(Cf + (size_t)(gm + 8) * ldc + gn) = make_float2(v10, v11);
            } else {
                bf162 h2, l2;
                split2(v00, v01, h2, l2);
                *reinterpret_cast<bf162*>(Chi + (size_t)gm * ldc + gn) = h2;
                *reinterpret_cast<bf162*>(Clo + (size_t)gm * ldc + gn) = l2;
                split2(v10, v11, h2, l2);
                *reinterpret_cast<bf162*>(Chi + (size_t)(gm + 8) * ldc + gn) = h2;
                *reinterpret_cast<bf162*>(Clo + (size_t)(gm + 8) * ldc + gn) = l2;
            }
        }
    }
}

__global__ void __launch_bounds__(256, 2)
kv_gemm(const bf16* __restrict__ Ahi, const bf16* __restrict__ Alo,
        const bf16* __restrict__ Bhi, const bf16* __restrict__ Blo,
        const float* __restrict__ bias_n, bf16* __restrict__ Chi, bf16* __restrict__ Clo) {
    extern __shared__ char smem[];
    gemm3_dev<1>(smem, Ahi, Alo, CTXD, Bhi, Blo, CTXD, CTXD,
                 blockIdx.y * 128, blockIdx.x * 128, 1.0f, bias_n,
                 nullptr, Chi, Clo, DMODEL);
}

__global__ void __launch_bounds__(256, 2)
oproj_gemm(const bf16* __restrict__ Ahi, const bf16* __restrict__ Alo,
           const bf16* __restrict__ Bhi, const bf16* __restrict__ Blo,
           const float* __restrict__ bias_n, float* __restrict__ C) {
    extern __shared__ char smem[];
    gemm3_dev<0>(smem, Ahi, Alo, DMODEL, Bhi, Blo, DMODEL, DMODEL,
                 blockIdx.y * 128, blockIdx.x * 128, 1.0f, bias_n,
                 C, nullptr, nullptr, DMODEL);
}

// ============================ fused flash attention ============================
#define FA_SMEM 160256
#define FA_LDS 104

__global__ void __launch_bounds__(256, 1)
fa_kernel(const bf16* __restrict__ Qhi, const bf16* __restrict__ Qlo,
          const bf16* __restrict__ Khi, const bf16* __restrict__ Klo,
          const bf16* __restrict__ Vhi, const bf16* __restrict__ Vlo,
          const float* __restrict__ biasBL, float scale,
          bf16* __restrict__ Ohi, bf16* __restrict__ Olo) {
    extern __shared__ char smem[];
    const int tid = threadIdx.x;
    const int wid = tid >> 5, lane = tid & 31;
    const int z = blockIdx.y;
    const int b = z >> 3, h = z & 7;
    const int q0 = blockIdx.x * 128;
    const size_t bSeq = (size_t)b * SEQ;
    const int hOff = h * HDIM;

    const uint32_t smBase = smem_u32(smem);
    const uint32_t KBASE = 53248u, VBASE = 106496u, TSTR = 13312u, BBASE = 159744u;

    for (int i = tid; i < 1536; i += 256) {
        int row = i / 12, col = i % 12;
        uint32_t so = ((uint32_t)row * FA_LDS + (uint32_t)col * 8u) * 2u;
        size_t go = (size_t)(q0 + row) * DMODEL + hOff + col * 8;
        cp16(smBase + so,           Qhi + go);
        cp16(smBase + 26624u + so,  Qlo + go);
    }
    CP_COMMIT();

    auto load_kv = [&](int c, int buf) {
        int l0 = c * 64;
        uint32_t kB = smBase + KBASE + (uint32_t)buf * 26624u;
        uint32_t vB = smBase + VBASE + (uint32_t)buf * 26624u;
        for (int i = tid; i < 768; i += 256) {
            int row = i / 12, col = i % 12;
            uint32_t so = ((uint32_t)row * FA_LDS + (uint32_t)col * 8u) * 2u;
            size_t go = (bSeq + l0 + row) * DMODEL + hOff + col * 8;
            cp16(kB + so,        Khi + go);
            cp16(kB + TSTR + so, Klo + go);
            cp16(vB + so,        Vhi + go);
            cp16(vB + TSTR + so, Vlo + go);
        }
        if (tid < 16)
            cp16(smBase + BBASE + (uint32_t)buf * 256u + (uint32_t)tid * 16u,
                 biasBL + bSeq + l0 + tid * 4);
    };
    load_kv(0, 0);
    CP_COMMIT();

    const uint32_t aRow = (uint32_t)(wid * 16 + (lane & 15)) * FA_LDS + (uint32_t)(lane >> 4) * 8u;
    const uint32_t bRow = (uint32_t)((lane & 7) + ((lane >> 4) * 8)) * FA_LDS
                        + (uint32_t)((lane >> 3) & 1) * 8u;
    const uint32_t vLaneRow = (uint32_t)((lane & 7) + ((lane >> 3) & 1) * 8);
    const uint32_t vLaneCol = (uint32_t)(lane >> 4) * 8u;

    float oacc[12][4];
    #pragma unroll
    for (int j = 0; j < 12; j++)
        #pragma unroll
        for (int k = 0; k < 4; k++) oacc[j][k] = 0.f;
    float m0 = -1e30f, m1 = -1e30f, l0s = 0.f, l1s = 0.f;

    for (int c = 0; c < 16; c++) {
        CP_WAIT0();
        __syncthreads();
        if (c + 1 < 16) { load_kv(c + 1, (c + 1) & 1); CP_COMMIT(); }

        const uint32_t kB = smBase + KBASE + (uint32_t)(c & 1) * 26624u;
        const uint32_t vB = smBase + VBASE + (uint32_t)(c & 1) * 26624u;
        const float* sbias = reinterpret_cast<const float*>(smem + BBASE + (c & 1) * 256);

        float s[8][4];
        #pragma unroll
        for (int j = 0; j < 8; j++)
            #pragma unroll
            for (int k = 0; k < 4; k++) s[j][k] = 0.f;

        #pragma unroll
        for (int ks = 0; ks < 6; ks++) {
            const uint32_t kcol = (uint32_t)ks * 16u;
            uint32_t qhiF[4], qloF[4], kk[4];
            uint32_t qoff = (aRow + kcol) * 2u;
            ldm_x4(qhiF, smBase + qoff);
            ldm_x4(qloF, smBase + 26624u + qoff);
            #pragma unroll
            for (int g = 0; g < 4; g++) {
                uint32_t off = (bRow + (uint32_t)g * 16u * FA_LDS + kcol) * 2u;
                ldm_x4(kk, kB + off);
                mma16816(s[2 * g],     qhiF, &kk[0]);
                mma16816(s[2 * g + 1], qhiF, &kk[2]);
                mma16816(s[2 * g],     qloF, &kk[0]);
                mma16816(s[2 * g + 1], qloF, &kk[2]);
                ldm_x4(kk, kB + TSTR + off);
                mma16816(s[2 * g],     qhiF, &kk[0]);
                mma16816(s[2 * g + 1], qhiF, &kk[2]);
            }
        }

        float mx0 = -1e30f, mx1 = -1e30f;
        #pragma unroll
        for (int nj = 0; nj < 8; nj++) {
            int cidx = nj * 8 + (lane & 3) * 2;
            float bj0 = sbias[cidx], bj1 = sbias[cidx + 1];
            s[nj][0] = s[nj][0] * scale + bj0;
            s[nj][1] = s[nj][1] * scale + bj1;
            s[nj][2] = s[nj][2] * scale + bj0;
            s[nj][3] = s[nj][3] * scale + bj1;
            mx0 = fmaxf(mx0, fmaxf(s[nj][0], s[nj][1]));
            mx1 = fmaxf(mx1, fmaxf(s[nj][2], s[nj][3]));
        }
        #pragma unroll
        for (int o = 1; o <= 2; o <<= 1) {
            mx0 = fmaxf(mx0, __shfl_xor_sync(0xffffffffu, mx0, o));
            mx1 = fmaxf(mx1, __shfl_xor_sync(0xffffffffu, mx1, o));
        }
        float mn0 = fmaxf(m0, mx0), mn1 = fmaxf(m1, mx1);
        float cor0 = __expf(m0 - mn0), cor1 = __expf(m1 - mn1);
        l0s *= cor0; l1s *= cor1;
        #pragma unroll
        for (int j = 0; j < 12; j++) {
            oacc[j][0] *= cor0; oacc[j][1] *= cor0;
            oacc[j][2] *= cor1; oacc[j][3] *= cor1;
        }
        m0 = mn0; m1 = mn1;

        float rs0 = 0.f, rs1 = 0.f;
        uint32_t phiF[4][4], ploF[4][4];
        #pragma unroll
        for (int t = 0; t < 4; t++) {
            float p00 = __expf(s[2 * t][0] - mn0);
            float p01 = __expf(s[2 * t][1] - mn0);
            float p10 = __expf(s[2 * t][2] - mn1);
            float p11 = __expf(s[2 * t][3] - mn1);
            float p20 = __expf(s[2 * t + 1][0] - mn0);
            float p21 = __expf(s[2 * t + 1][1] - mn0);
            float p30 = __expf(s[2 * t + 1][2] - mn1);
            float p31 = __expf(s[2 * t + 1][3] - mn1);
            rs0 += p00 + p01 + p20 + p21;
            rs1 += p10 + p11 + p30 + p31;
            splitpack(p00, p01, phiF[t][0], ploF[t][0]);
            splitpack(p10, p11, phiF[t][1], ploF[t][1]);
            splitpack(p20, p21, phiF[t][2], ploF[t][2]);
            splitpack(p30, p31, phiF[t][3], ploF[t][3]);
        }
        #pragma unroll
        for (int o = 1; o <= 2; o <<= 1) {
            rs0 += __shfl_xor_sync(0xffffffffu, rs0, o);
            rs1 += __shfl_xor_sync(0xffffffffu, rs1, o);
        }
        l0s += rs0; l1s += rs1;

        #pragma unroll
        for (int t = 0; t < 4; t++) {
            uint32_t vv[4];
            #pragma unroll
            for (int g = 0; g < 6; g++) {
                uint32_t off = (((uint32_t)t * 16u + vLaneRow) * FA_LDS
                                + (uint32_t)g * 16u + vLaneCol) * 2u;
                ldm_x4_t(vv, vB + off);
                mma16816(oacc[2 * g],     phiF[t], &vv[0]);
                mma16816(oacc[2 * g + 1], phiF[t], &vv[2]);
                mma16816(oacc[2 * g],     ploF[t], &vv[0]);
                mma16816(oacc[2 * g + 1], ploF[t], &vv[2]);
                ldm_x4_t(vv, vB + TSTR + off);
                mma16816(oacc[2 * g],     phiF[t], &vv[0]);
                mma16816(oacc[2 * g + 1], phiF[t], &vv[2]);
            }
        }
    }

    float inv0 = 1.0f / l0s, inv1 = 1.0f / l1s;
    const int q = q0 + wid * 16 + (lane >> 2);
    #pragma unroll
    for (int j = 0; j < 12; j++) {
        int n = j * 8 + (lane & 3) * 2;
        size_t o0 = ((size_t)(b * NQ + q)) * DMODEL + hOff + n;
        size_t o1 = o0 + (size_t)8 * DMODEL;
        bf162 h2, l2;
        split2(oacc[j][0] * inv0, oacc[j][1] * inv0, h2, l2);
        *reinterpret_cast<bf162*>(Ohi + o0) = h2;
        *reinterpret_cast<bf162*>(Olo + o0) = l2;
        split2(oacc[j][2] * inv1, oacc[j][3] * inv1, h2, l2);
        *reinterpret_cast<bf162*>(Ohi + o1) = h2;
        *reinterpret_cast<bf162*>(Olo + o1) = l2;
    }
}

// ============================ LayerNorm / misc ============================
__device__ __forceinline__ void ln_stats(const float* __restrict__ xr, int ncols,
                                         float& mu, float& rs, float* s1, float* s2) {
    float sum = 0.f, sumsq = 0.f;
    for (int i = threadIdx.x; i < ncols; i += blockDim.x) {
        float v = xr[i];
        sum += v; sumsq += v * v;
    }
    #pragma unroll
    for (int o = 16; o; o >>= 1) {
        sum   += __shfl_xor_sync(0xffffffffu, sum, o);
        sumsq += __shfl_xor_sync(0xffffffffu, sumsq, o);
    }
    int wid = threadIdx.x >> 5, lid = threadIdx.x & 31;
    if (lid == 0) { s1[wid] = sum; s2[wid] = sumsq; }
    __syncthreads();
    if (threadIdx.x < 32) {
        int nw = blockDim.x >> 5;
        float a = (lid < nw) ? s1[lid] : 0.f;
        float c = (lid < nw) ? s2[lid] : 0.f;
        #pragma unroll
        for (int o = 16; o; o >>= 1) {
            a += __shfl_xor_sync(0xffffffffu, a, o);
            c += __shfl_xor_sync(0xffffffffu, c, o);
        }
        if (lid == 0) { s1[0] = a; s2[0] = c; }
    }
    __syncthreads();
    float inv_n = 1.0f / (float)ncols;
    mu = s1[0] * inv_n;
    float var = s2[0] * inv_n - mu * mu;
    rs = rsqrtf(var + 1e-5f);
}

__global__ void ln_kernel(const float* __restrict__ x, const float* __restrict__ w,
                          const float* __restrict__ b, float* __restrict__ out, int ncols) {
    __shared__ float s1[32], s2[32];
    const size_t row = blockIdx.x;
    const float* xr = x + row * (size_t)ncols;
    float mu, rs;
    ln_stats(xr, ncols, mu, rs, s1, s2);
    float* orow = out + row * (size_t)ncols;
    for (int i = threadIdx.x; i < ncols; i += blockDim.x)
        orow[i] = (xr[i] - mu) * rs * w[i] + b[i];
}

__global__ void ln_split_kernel(const float* __restrict__ x, const float* __restrict__ w,
                                const float* __restrict__ b,
                                bf16* __restrict__ hi, bf16* __restrict__ lo, int ncols) {
    __shared__ float s1[32], s2[32];
    const size_t row = blockIdx.x;
    const float* xr = x + row * (size_t)ncols;
    float mu, rs;
    ln_stats(xr, ncols, mu, rs, s1, s2);
    bf16* hrow = hi + row * (size_t)ncols;
    bf16* lrow = lo + row * (size_t)ncols;
    for (int i = threadIdx.x; i < ncols; i += blockDim.x) {
        float y = (xr[i] - mu) * rs * w[i] + b[i];
        bf16 hh = __float2bfloat16(y);
        hrow[i] = hh;
        lrow[i] = __float2bfloat16(y - __bfloat162float(hh));
    }
}

__global__ void split_kernel(const float* __restrict__ x,
                             bf16* __restrict__ hi, bf16* __restrict__ lo, int n) {
    int i = blockIdx.x * blockDim.x + threadIdx.x;
    if (i < n) {
        float v = x[i];
        bf16 h = __float2bfloat16(v);
        hi[i] = h;
        lo[i] = __float2bfloat16(v - __bfloat162float(h));
    }
}

__global__ void bias_kernel(const float* __restrict__ size_in, const float* __restrict__ mask,
                            float* __restrict__ bias, int n) {
    int i = blockIdx.x * blockDim.x + threadIdx.x;
    if (i < n) {
        float s = size_in[i];
        s = (s < 0.5f) ? 1.0f : s;
        bias[i] = logf(s) + mask[i];
    }
}

// ============================ SIMT GEMM (Q-proj only) ============================
#define TBM 64
#define TBN 64
#define TBK 16
#define SPAD 4

__global__ void __launch_bounds__(256)
gemm_nt_kernel(const float* __restrict__ A, int lda,
               const float* __restrict__ B, int ldb,
               float* __restrict__ C, int ldc,
               int M, int N, int K, float alpha, const float* __restrict__ bias_n) {
    __shared__ __align__(16) float As[TBK][TBM + SPAD];
    __shared__ __align__(16) float Bs[TBK][TBN + SPAD];
    const int m0 = blockIdx.y * TBM;
    const int n0 = blockIdx.x * TBN;
    const int t  = threadIdx.x;
    const int tx = t & 15, ty = t >> 4;
    float acc[4][4] = {};
    for (int k0 = 0; k0 < K; k0 += TBK) {
        {
            int col = t & 15, rowb = t >> 4;
            #pragma unroll
            for (int i = 0; i < 4; i++) {
                int rr = rowb + i * 16;
                As[col][rr] = A[(size_t)(m0 + rr) * lda + k0 + col];
            }
        }
        {
            int col = t & 15, rowb = t >> 4;
            #pragma unroll
            for (int i = 0; i < 4; i++) {
                int nn = rowb + i * 16;
                Bs[col][nn] = B[(size_t)(n0 + nn) * ldb + k0 + col];
            }
        }
        __syncthreads();
        #pragma unroll
        for (int kk = 0; kk < TBK; kk++) {
            float4 av = *reinterpret_cast<const float4*>(&As[kk][ty * 4]);
            float4 bv = *reinterpret_cast<const float4*>(&Bs[kk][tx * 4]);
            float a[4] = {av.x, av.y, av.z, av.w};
            float b[4] = {bv.x, bv.y, bv.z, bv.w};
            #pragma unroll
            for (int i = 0; i < 4; i++)
                #pragma unroll
                for (int j = 0; j < 4; j++)
                    acc[i][j] += a[i] * b[j];
        }
        __syncthreads();
    }
    #pragma unroll
    for (int i = 0; i < 4; i++) {
        int gm = m0 + ty * 4 + i;
        #pragma unroll
        for (int j = 0; j < 4; j++) {
            int gn = n0 + tx * 4 + j;
            float v = alpha * acc[i][j];
            if (bias_n) v += bias_n[gn];
            C[(size_t)gm * ldc + gn] = v;
        }
    }
}

// ============================ launch ============================
extern "C" void kernel_launch(void* const* d_in, const int* in_sizes, int n_in,
                              void* d_out, int out_size) {
    const float* x     = (const float*)d_in[0];
    const float* sizei = (const float*)d_in[1];
    const float* amask = (const float*)d_in[2];
    const float* query = (const float*)d_in[3];
    const float* ln_q_w = (const float*)d_in[4];
    const float* ln_q_b = (const float*)d_in[5];
    const float* ln_k_w = (const float*)d_in[6];
    const float* ln_k_b = (const float*)d_in[7];
    const float* Wq = (const float*)d_in[8];
    const float* Wk = (const float*)d_in[9];
    const float* Wv = (const float*)d_in[10];
    const float* bq = (const float*)d_in[11];
    const float* bk = (const float*)d_in[12];
    const float* bv = (const float*)d_in[13];
    const float* Wo = (const float*)d_in[14];
    const float* bo = (const float*)d_in[15];
    float* out = (float*)d_out;

    bf16 *xhi, *xlo, *wkhi, *wklo, *wvhi, *wvlo, *wohi, *wolo;
    bf16 *khhi, *khlo, *vhhi, *vhlo, *qhhi, *qhlo, *aohi, *aolo;
    float *qln, *qh, *bias;
    cudaGetSymbolAddress((void**)&xhi, g_xhi);
    cudaGetSymbolAddress((void**)&xlo, g_xlo);
    cudaGetSymbolAddress((void**)&wkhi, g_wkhi);
    cudaGetSymbolAddress((void**)&wklo, g_wklo);
    cudaGetSymbolAddress((void**)&wvhi, g_wvhi);
    cudaGetSymbolAddress((void**)&wvlo, g_wvlo);
    cudaGetSymbolAddress((void**)&wohi, g_wohi);
    cudaGetSymbolAddress((void**)&wolo, g_wolo);
    cudaGetSymbolAddress((void**)&khhi, g_khhi);
    cudaGetSymbolAddress((void**)&khlo, g_khlo);
    cudaGetSymbolAddress((void**)&vhhi, g_vhhi);
    cudaGetSymbolAddress((void**)&vhlo, g_vhlo);
    cudaGetSymbolAddress((void**)&qhhi, g_qhhi);
    cudaGetSymbolAddress((void**)&qhlo, g_qhlo);
    cudaGetSymbolAddress((void**)&aohi, g_aohi);
    cudaGetSymbolAddress((void**)&aolo, g_aolo);
    cudaGetSymbolAddress((void**)&qln, g_qln);
    cudaGetSymbolAddress((void**)&qh, g_qh);
    cudaGetSymbolAddress((void**)&bias, g_bias);

    cudaFuncSetAttribute(kv_gemm,    cudaFuncAttributeMaxDynamicSharedMemorySize, G3_SMEM);
    cudaFuncSetAttribute(oproj_gemm, cudaFuncAttributeMaxDynamicSharedMemorySize, G3_SMEM);
    cudaFuncSetAttribute(fa_kernel,  cudaFuncAttributeMaxDynamicSharedMemorySize, FA_SMEM);

    const float scale = 0.10206207261596575f;  // 1/sqrt(96)

    // launch order: index 3 (ncu-profiled) = kv_gemm(K)
    ln_split_kernel<<<MROWS, 256>>>(x, ln_k_w, ln_k_b, xhi, xlo, CTXD);               // 0
    split_kernel<<<(DMODEL * CTXD + 255) / 256, 256>>>(Wk, wkhi, wklo, DMODEL * CTXD); // 1
    split_kernel<<<(DMODEL * CTXD + 255) / 256, 256>>>(Wv, wvhi, wvlo, DMODEL * CTXD); // 2
    {
        dim3 grid(DMODEL / 128, MROWS / 128);
        kv_gemm<<<grid, 256, G3_SMEM>>>(xhi, xlo, wkhi, wklo, bk, khhi, khlo);         // 3 (profiled)
        kv_gemm<<<grid, 256, G3_SMEM>>>(xhi, xlo, wvhi, wvlo, bv, vhhi, vhlo);         // 4
    }
    ln_kernel<<<NQ, 256>>>(query, ln_q_w, ln_q_b, qln, DMODEL);                        // 5
    split_kernel<<<(DMODEL * DMODEL + 255) / 256, 256>>>(Wo, wohi, wolo, DMODEL * DMODEL); // 6
    bias_kernel<<<(MROWS + 255) / 256, 256>>>(sizei, amask, bias, MROWS);              // 7
    gemm_nt_kernel<<<dim3(DMODEL / TBN, NQ / TBM), 256>>>(                             // 8
        qln, DMODEL, Wq, DMODEL, qh, DMODEL, NQ, DMODEL, DMODEL, 1.0f, bq);
    split_kernel<<<(NQ * DMODEL + 255) / 256, 256>>>(qh, qhhi, qhlo, NQ * DMODEL);     // 9

    fa_kernel<<<dim3(NQ / 128, NZ), 256, FA_SMEM>>>(                                   // 10
        qhhi, qhlo, khhi, khlo, vhhi, vhlo, bias, scale, aohi, aolo);

    oproj_gemm<<<dim3(DMODEL / 128, BATCH * NQ / 128), 256, G3_SMEM>>>(                // 11
        aohi, aolo, wohi, wolo, bo, out);
}

// round 7
// speedup vs baseline: 3.1106x; 1.0724x over previous
#include <cuda_runtime.h>
#include <cuda_bf16.h>
#include <cstdint>

#define BATCH     32
#define SEQ       1024
#define CTXD      1024
#define DMODEL    768
#define NHEAD     8
#define HDIM      96
#define NQ        256
#define MROWS     (BATCH * SEQ)   // 32768
#define NZ        (BATCH * NHEAD) // 256

typedef __nv_bfloat16 bf16;
typedef __nv_bfloat162 bf162;

// ============================ device scratch ============================
__device__ bf16 g_xhi[MROWS * CTXD];
__device__ bf16 g_xlo[MROWS * CTXD];
__device__ bf16 g_wkhi[DMODEL * CTXD];
__device__ bf16 g_wklo[DMODEL * CTXD];
__device__ bf16 g_wvhi[DMODEL * CTXD];
__device__ bf16 g_wvlo[DMODEL * CTXD];
__device__ bf16 g_wohi[DMODEL * DMODEL];
__device__ bf16 g_wolo[DMODEL * DMODEL];
__device__ bf16 g_khhi[MROWS * DMODEL];
__device__ bf16 g_khlo[MROWS * DMODEL];
__device__ bf16 g_vhhi[MROWS * DMODEL];
__device__ bf16 g_vhlo[MROWS * DMODEL];
__device__ bf16 g_qhhi[NQ * DMODEL];
__device__ bf16 g_qhlo[NQ * DMODEL];
__device__ bf16 g_aohi[BATCH * NQ * DMODEL];
__device__ bf16 g_aolo[BATCH * NQ * DMODEL];
__device__ float g_qln[NQ * DMODEL];
__device__ float g_qh[NQ * DMODEL];
__device__ float g_bias[MROWS];

// ============================ asm helpers ============================
__device__ __forceinline__ uint32_t smem_u32(const void* p) {
    uint32_t a;
    asm("{ .reg .u64 t; cvta.to.shared.u64 t, %1; cvt.u32.u64 %0, t; }" : "=r"(a) : "l"(p));
    return a;
}
__device__ __forceinline__ void ldm_x4(uint32_t* r, uint32_t addr) {
    asm volatile("ldmatrix.sync.aligned.m8n8.x4.shared.b16 {%0,%1,%2,%3}, [%4];"
                 : "=r"(r[0]), "=r"(r[1]), "=r"(r[2]), "=r"(r[3]) : "r"(addr));
}
__device__ __forceinline__ void ldm_x4_t(uint32_t* r, uint32_t addr) {
    asm volatile("ldmatrix.sync.aligned.m8n8.x4.trans.shared.b16 {%0,%1,%2,%3}, [%4];"
                 : "=r"(r[0]), "=r"(r[1]), "=r"(r[2]), "=r"(r[3]) : "r"(addr));
}
__device__ __forceinline__ void mma16816(float* c, const uint32_t* a, const uint32_t* b) {
    asm volatile("mma.sync.aligned.m16n8k16.row.col.f32.bf16.bf16.f32 "
                 "{%0,%1,%2,%3}, {%4,%5,%6,%7}, {%8,%9}, {%0,%1,%2,%3};"
                 : "+f"(c[0]), "+f"(c[1]), "+f"(c[2]), "+f"(c[3])
                 : "r"(a[0]), "r"(a[1]), "r"(a[2]), "r"(a[3]), "r"(b[0]), "r"(b[1]));
}
__device__ __forceinline__ void cp16(uint32_t dst, const void* src) {
    asm volatile("cp.async.cg.shared.global [%0], [%1], 16;" :: "r"(dst), "l"(src));
}
#define CP_COMMIT() asm volatile("cp.async.commit_group;")
#define CP_WAIT0()  asm volatile("cp.async.wait_group 0;")

__device__ __forceinline__ void split2(float v0, float v1, bf162& h2, bf162& l2) {
    bf16 h0 = __float2bfloat16(v0);
    bf16 h1 = __float2bfloat16(v1);
    h2 = bf162(h0, h1);
    l2 = bf162(__float2bfloat16(v0 - __bfloat162float(h0)),
               __float2bfloat16(v1 - __bfloat162float(h1)));
}
__device__ __forceinline__ void splitpack(float v0, float v1, uint32_t& hi, uint32_t& lo) {
    bf162 h2, l2;
    split2(v0, v1, h2, l2);
    hi = *reinterpret_cast<uint32_t*>(&h2);
    lo = *reinterpret_cast<uint32_t*>(&l2);
}

// ============================ split-bf16 NT GEMM ============================
// k-chunk 32, double-buffered, 2 CTAs/SM (2 x 80KB = 160KB smem).
// smem layout (bytes): A: buf*20480 + term*10240 ; B: 40960 + buf*20480 + term*10240
#define G3_SMEM 81920
#define LDS_BF 40

template<int EPI>  // 0: fp32 out, 1: split bf16 out
__device__ __forceinline__ void gemm3_dev(
    char* smem,
    const bf16* __restrict__ Ahi, const bf16* __restrict__ Alo, int lda,
    const bf16* __restrict__ Bhi, const bf16* __restrict__ Blo, int ldb,
    int K, int m0, int n0, float alpha, const float* __restrict__ bias_n,
    float* __restrict__ Cf, bf16* __restrict__ Chi, bf16* __restrict__ Clo, int ldc)
{
    const int tid  = threadIdx.x;
    const int wid  = tid >> 5;
    const int lane = tid & 31;
    const int wm = (wid & 3) * 32;
    const int wn = (wid >> 2) * 64;

    const uint32_t smBase = smem_u32(smem);
    const uint32_t aRow = (uint32_t)(wm + (lane & 15)) * LDS_BF + (uint32_t)(lane >> 4) * 8u;
    const uint32_t bRow = (uint32_t)(wn + (lane & 7) + ((lane >> 4) * 8)) * LDS_BF
                        + (uint32_t)((lane >> 3) & 1) * 8u;

    float acc[2][8][4];
    #pragma unroll
    for (int i = 0; i < 2; i++)
        #pragma unroll
        for (int j = 0; j < 8; j++)
            #pragma unroll
            for (int k = 0; k < 4; k++) acc[i][j][k] = 0.f;

    const int r  = tid >> 2;
    const int cc = tid & 3;
    const int nchunks = K >> 5;

    auto load_chunk = [&](int k0, int buf) {
        uint32_t aB = smBase + (uint32_t)buf * 20480u;
        uint32_t bB = smBase + 40960u + (uint32_t)buf * 20480u;
        #pragma unroll
        for (int h = 0; h < 2; h++) {
            int rr = r + h * 64;
            uint32_t so = ((uint32_t)rr * LDS_BF + (uint32_t)cc * 8u) * 2u;
            size_t ga = (size_t)(m0 + rr) * lda + k0 + cc * 8;
            size_t gb = (size_t)(n0 + rr) * ldb + k0 + cc * 8;
            cp16(aB + so,           Ahi + ga);
            cp16(aB + 10240u + so,  Alo + ga);
            cp16(bB + so,           Bhi + gb);
            cp16(bB + 10240u + so,  Blo + gb);
        }
    };

    load_chunk(0, 0);
    CP_COMMIT();

    for (int c = 0; c < nchunks; c++) {
        CP_WAIT0();
        __syncthreads();
        if (c + 1 < nchunks) { load_chunk((c + 1) << 5, (c + 1) & 1); CP_COMMIT(); }

        uint32_t aB = smBase + (uint32_t)(c & 1) * 20480u;
        uint32_t bB = smBase + 40960u + (uint32_t)(c & 1) * 20480u;
        #pragma unroll
        for (int ks = 0; ks < 2; ks++) {
            const uint32_t kcol = (uint32_t)ks * 16u;
            uint32_t ahi[2][4], alo[2][4], b[4][4];
            #pragma unroll
            for (int mi = 0; mi < 2; mi++) {
                uint32_t off = (aRow + (uint32_t)mi * 16u * LDS_BF + kcol) * 2u;
                ldm_x4(ahi[mi], aB + off);
                ldm_x4(alo[mi], aB + 10240u + off);
            }
            #pragma unroll
            for (int g = 0; g < 4; g++) {
                uint32_t off = (bRow + (uint32_t)g * 16u * LDS_BF + kcol) * 2u;
                ldm_x4(b[g], bB + off);
            }
            #pragma unroll
            for (int mi = 0; mi < 2; mi++)
                #pragma unroll
                for (int nj = 0; nj < 8; nj++) {
                    const uint32_t* bf = &b[nj >> 1][(nj & 1) * 2];
                    mma16816(acc[mi][nj], ahi[mi], bf);
                    mma16816(acc[mi][nj], alo[mi], bf);
                }
            #pragma unroll
            for (int g = 0; g < 4; g++) {
                uint32_t off = (bRow + (uint32_t)g * 16u * LDS_BF + kcol) * 2u;
                ldm_x4(b[g], bB + 10240u + off);
            }
            #pragma unroll
            for (int mi = 0; mi < 2; mi++)
                #pragma unroll
                for (int nj = 0; nj < 8; nj++)
                    mma16816(acc[mi][nj], ahi[mi], &b[nj >> 1][(nj & 1) * 2]);
        }
        __syncthreads();
    }

    #pragma unroll
    for (int mi = 0; mi < 2; mi++) {
        int gm = m0 + wm + mi * 16 + (lane >> 2);
        #pragma unroll
        for (int nj = 0; nj < 8; nj++) {
            int gn = n0 + wn + nj * 8 + (lane & 3) * 2;
            float b0 = bias_n ? bias_n[gn]     : 0.f;
            float b1 = bias_n ? bias_n[gn + 1] : 0.f;
            float v00 = alpha * acc[mi][nj][0] + b0;
            float v01 = alpha * acc[mi][nj][1] + b1;
            float v10 = alpha * acc[mi][nj][2] + b0;
            float v11 = alpha * acc[mi][nj][3] + b1;
            if (EPI == 0) {
                *reinterpret_cast<float2*>(Cf + (size_t)gm * ldc + gn)       = make_float2(v00, v01);
                *reinterpret_cast<float2*>(Cf + (size_t)(gm + 8) * ldc + gn) = make_float2(v10, v11);
            } else {
                bf162 h2, l2;
                split2(v00, v01, h2, l2);
                *reinterpret_cast<bf162*>(Chi + (size_t)gm * ldc + gn) = h2;
                *reinterpret_cast<bf162*>(Clo + (size_t)gm * ldc + gn) = l2;
                split2(v10, v11, h2, l2);
                *reinterpret_cast<bf162*>(Chi + (size_t)(gm + 8) * ldc + gn) = h2;
                *reinterpret_cast<bf162*>(Clo + (size_t)(gm + 8) * ldc + gn) = l2;
            }
        }
    }
}

__global__ void __launch_bounds__(256, 2)
kv_gemm(const bf16* __restrict__ Ahi, const bf16* __restrict__ Alo,
        const bf16* __restrict__ Bhi, const bf16* __restrict__ Blo,
        const float* __restrict__ bias_n, bf16* __restrict__ Chi, bf16* __restrict__ Clo) {
    extern __shared__ char smem[];
    gemm3_dev<1>(smem, Ahi, Alo, CTXD, Bhi, Blo, CTXD, CTXD,
                 blockIdx.y * 128, blockIdx.x * 128, 1.0f, bias_n,
                 nullptr, Chi, Clo, DMODEL);
}

__global__ void __launch_bounds__(256, 2)
oproj_gemm(const bf16* __restrict__ Ahi, const bf16* __restrict__ Alo,
           const bf16* __restrict__ Bhi, const bf16* __restrict__ Blo,
           const float* __restrict__ bias_n, float* __restrict__ C) {
    extern __shared__ char smem[];
    gemm3_dev<0>(smem, Ahi, Alo, DMODEL, Bhi, Blo, DMODEL, DMODEL,
                 blockIdx.y * 128, blockIdx.x * 128, 1.0f, bias_n,
                 C, nullptr, nullptr, DMODEL);
}

// ============================ fused flash attention ============================
#define FA_SMEM 160256
#define FA_LDS 104

__global__ void __launch_bounds__(256, 1)
fa_kernel(const bf16* __restrict__ Qhi, const bf16* __restrict__ Qlo,
          const bf16* __restrict__ Khi, const bf16* __restrict__ Klo,
          const bf16* __restrict__ Vhi, const bf16* __restrict__ Vlo,
          const float* __restrict__ biasBL, float scale,
          bf16* __restrict__ Ohi, bf16* __restrict__ Olo) {
    extern __shared__ char smem[];
    const int tid = threadIdx.x;
    const int wid = tid >> 5, lane = tid & 31;
    const int z = blockIdx.y;
    const int b = z >> 3, h = z & 7;
    const int q0 = blockIdx.x * 128;
    const size_t bSeq = (size_t)b * SEQ;
    const int hOff = h * HDIM;

    const uint32_t smBase = smem_u32(smem);
    const uint32_t KBASE = 53248u, VBASE = 106496u, TSTR = 13312u, BBASE = 159744u;

    for (int i = tid; i < 1536; i += 256) {
        int row = i / 12, col = i % 12;
        uint32_t so = ((uint32_t)row * FA_LDS + (uint32_t)col * 8u) * 2u;
        size_t go = (size_t)(q0 + row) * DMODEL + hOff + col * 8;
        cp16(smBase + so,           Qhi + go);
        cp16(smBase + 26624u + so,  Qlo + go);
    }
    CP_COMMIT();

    auto load_kv = [&](int c, int buf) {
        int l0 = c * 64;
        uint32_t kB = smBase + KBASE + (uint32_t)buf * 26624u;
        uint32_t vB = smBase + VBASE + (uint32_t)buf * 26624u;
        for (int i = tid; i < 768; i += 256) {
            int row = i / 12, col = i % 12;
            uint32_t so = ((uint32_t)row * FA_LDS + (uint32_t)col * 8u) * 2u;
            size_t go = (bSeq + l0 + row) * DMODEL + hOff + col * 8;
            cp16(kB + so,        Khi + go);
            cp16(kB + TSTR + so, Klo + go);
            cp16(vB + so,        Vhi + go);
            cp16(vB + TSTR + so, Vlo + go);
        }
        if (tid < 16)
            cp16(smBase + BBASE + (uint32_t)buf * 256u + (uint32_t)tid * 16u,
                 biasBL + bSeq + l0 + tid * 4);
    };
    load_kv(0, 0);
    CP_COMMIT();

    const uint32_t aRow = (uint32_t)(wid * 16 + (lane & 15)) * FA_LDS + (uint32_t)(lane >> 4) * 8u;
    const uint32_t bRow = (uint32_t)((lane & 7) + ((lane >> 4) * 8)) * FA_LDS
                        + (uint32_t)((lane >> 3) & 1) * 8u;
    const uint32_t vLaneRow = (uint32_t)((lane & 7) + ((lane >> 3) & 1) * 8);
    const uint32_t vLaneCol = (uint32_t)(lane >> 4) * 8u;

    float oacc[12][4];
    #pragma unroll
    for (int j = 0; j < 12; j++)
        #pragma unroll
        for (int k = 0; k < 4; k++) oacc[j][k] = 0.f;
    float m0 = -1e30f, m1 = -1e30f, l0s = 0.f, l1s = 0.f;

    for (int c = 0; c < 16; c++) {
        CP_WAIT0();
        __syncthreads();
        if (c + 1 < 16) { load_kv(c + 1, (c + 1) & 1); CP_COMMIT(); }

        const uint32_t kB = smBase + KBASE + (uint32_t)(c & 1) * 26624u;
        const uint32_t vB = smBase + VBASE + (uint32_t)(c & 1) * 26624u;
        const float* sbias = reinterpret_cast<const float*>(smem + BBASE + (c & 1) * 256);

        float s[8][4];
        #pragma unroll
        for (int j = 0; j < 8; j++)
            #pragma unroll
            for (int k = 0; k < 4; k++) s[j][k] = 0.f;

        #pragma unroll
        for (int ks = 0; ks < 6; ks++) {
            const uint32_t kcol = (uint32_t)ks * 16u;
            uint32_t qhiF[4], qloF[4], kk[4];
            uint32_t qoff = (aRow + kcol) * 2u;
            ldm_x4(qhiF, smBase + qoff);
            ldm_x4(qloF, smBase + 26624u + qoff);
            #pragma unroll
            for (int g = 0; g < 4; g++) {
                uint32_t off = (bRow + (uint32_t)g * 16u * FA_LDS + kcol) * 2u;
                ldm_x4(kk, kB + off);
                mma16816(s[2 * g],     qhiF, &kk[0]);
                mma16816(s[2 * g + 1], qhiF, &kk[2]);
                mma16816(s[2 * g],     qloF, &kk[0]);
                mma16816(s[2 * g + 1], qloF, &kk[2]);
                ldm_x4(kk, kB + TSTR + off);
                mma16816(s[2 * g],     qhiF, &kk[0]);
                mma16816(s[2 * g + 1], qhiF, &kk[2]);
            }
        }

        float mx0 = -1e30f, mx1 = -1e30f;
        #pragma unroll
        for (int nj = 0; nj < 8; nj++) {
            int cidx = nj * 8 + (lane & 3) * 2;
            float bj0 = sbias[cidx], bj1 = sbias[cidx + 1];
            s[nj][0] = s[nj][0] * scale + bj0;
            s[nj][1] = s[nj][1] * scale + bj1;
            s[nj][2] = s[nj][2] * scale + bj0;
            s[nj][3] = s[nj][3] * scale + bj1;
            mx0 = fmaxf(mx0, fmaxf(s[nj][0], s[nj][1]));
            mx1 = fmaxf(mx1, fmaxf(s[nj][2], s[nj][3]));
        }
        #pragma unroll
        for (int o = 1; o <= 2; o <<= 1) {
            mx0 = fmaxf(mx0, __shfl_xor_sync(0xffffffffu, mx0, o));
            mx1 = fmaxf(mx1, __shfl_xor_sync(0xffffffffu, mx1, o));
        }
        float mn0 = fmaxf(m0, mx0), mn1 = fmaxf(m1, mx1);
        float cor0 = __expf(m0 - mn0), cor1 = __expf(m1 - mn1);
        l0s *= cor0; l1s *= cor1;
        #pragma unroll
        for (int j = 0; j < 12; j++) {
            oacc[j][0] *= cor0; oacc[j][1] *= cor0;
            oacc[j][2] *= cor1; oacc[j][3] *= cor1;
        }
        m0 = mn0; m1 = mn1;

        float rs0 = 0.f, rs1 = 0.f;
        uint32_t phiF[4][4], ploF[4][4];
        #pragma unroll
        for (int t = 0; t < 4; t++) {
            float p00 = __expf(s[2 * t][0] - mn0);
            float p01 = __expf(s[2 * t][1] - mn0);
            float p10 = __expf(s[2 * t][2] - mn1);
            float p11 = __expf(s[2 * t][3] - mn1);
            float p20 = __expf(s[2 * t + 1][0] - mn0);
            float p21 = __expf(s[2 * t + 1][1] - mn0);
            float p30 = __expf(s[2 * t + 1][2] - mn1);
            float p31 = __expf(s[2 * t + 1][3] - mn1);
            rs0 += p00 + p01 + p20 + p21;
            rs1 += p10 + p11 + p30 + p31;
            splitpack(p00, p01, phiF[t][0], ploF[t][0]);
            splitpack(p10, p11, phiF[t][1], ploF[t][1]);
            splitpack(p20, p21, phiF[t][2], ploF[t][2]);
            splitpack(p30, p31, phiF[t][3], ploF[t][3]);
        }
        #pragma unroll
        for (int o = 1; o <= 2; o <<= 1) {
            rs0 += __shfl_xor_sync(0xffffffffu, rs0, o);
            rs1 += __shfl_xor_sync(0xffffffffu, rs1, o);
        }
        l0s += rs0; l1s += rs1;

        #pragma unroll
        for (int t = 0; t < 4; t++) {
            uint32_t vv[4];
            #pragma unroll
            for (int g = 0; g < 6; g++) {
                uint32_t off = (((uint32_t)t * 16u + vLaneRow) * FA_LDS
                                + (uint32_t)g * 16u + vLaneCol) * 2u;
                ldm_x4_t(vv, vB + off);
                mma16816(oacc[2 * g],     phiF[t], &vv[0]);
                mma16816(oacc[2 * g + 1], phiF[t], &vv[2]);
                mma16816(oacc[2 * g],     ploF[t], &vv[0]);
                mma16816(oacc[2 * g + 1], ploF[t], &vv[2]);
                ldm_x4_t(vv, vB + TSTR + off);
                mma16816(oacc[2 * g],     phiF[t], &vv[0]);
                mma16816(oacc[2 * g + 1], phiF[t], &vv[2]);
            }
        }
    }

    float inv0 = 1.0f / l0s, inv1 = 1.0f / l1s;
    const int q = q0 + wid * 16 + (lane >> 2);
    #pragma unroll
    for (int j = 0; j < 12; j++) {
        int n = j * 8 + (lane & 3) * 2;
        size_t o0 = ((size_t)(b * NQ + q)) * DMODEL + hOff + n;
        size_t o1 = o0 + (size_t)8 * DMODEL;
        bf162 h2, l2;
        split2(oacc[j][0] * inv0, oacc[j][1] * inv0, h2, l2);
        *reinterpret_cast<bf162*>(Ohi + o0) = h2;
        *reinterpret_cast<bf162*>(Olo + o0) = l2;
        split2(oacc[j][2] * inv1, oacc[j][3] * inv1, h2, l2);
        *reinterpret_cast<bf162*>(Ohi + o1) = h2;
        *reinterpret_cast<bf162*>(Olo + o1) = l2;
    }
}

// ============================ LayerNorm / misc ============================
__device__ __forceinline__ void ln_stats(const float* __restrict__ xr, int ncols,
                                         float& mu, float& rs, float* s1, float* s2) {
    float sum = 0.f, sumsq = 0.f;
    for (int i = threadIdx.x; i < ncols; i += blockDim.x) {
        float v = xr[i];
        sum += v; sumsq += v * v;
    }
    #pragma unroll
    for (int o = 16; o; o >>= 1) {
        sum   += __shfl_xor_sync(0xffffffffu, sum, o);
        sumsq += __shfl_xor_sync(0xffffffffu, sumsq, o);
    }
    int wid = threadIdx.x >> 5, lid = threadIdx.x & 31;
    if (lid == 0) { s1[wid] = sum; s2[wid] = sumsq; }
    __syncthreads();
    if (threadIdx.x < 32) {
        int nw = blockDim.x >> 5;
        float a = (lid < nw) ? s1[lid] : 0.f;
        float c = (lid < nw) ? s2[lid] : 0.f;
        #pragma unroll
        for (int o = 16; o; o >>= 1) {
            a += __shfl_xor_sync(0xffffffffu, a, o);
            c += __shfl_xor_sync(0xffffffffu, c, o);
        }
        if (lid == 0) { s1[0] = a; s2[0] = c; }
    }
    __syncthreads();
    float inv_n = 1.0f / (float)ncols;
    mu = s1[0] * inv_n;
    float var = s2[0] * inv_n - mu * mu;
    rs = rsqrtf(var + 1e-5f);
}

__global__ void ln_kernel(const float* __restrict__ x, const float* __restrict__ w,
                          const float* __restrict__ b, float* __restrict__ out, int ncols) {
    __shared__ float s1[32], s2[32];
    const size_t row = blockIdx.x;
    const float* xr = x + row * (size_t)ncols;
    float mu, rs;
    ln_stats(xr, ncols, mu, rs, s1, s2);
    float* orow = out + row * (size_t)ncols;
    for (int i = threadIdx.x; i < ncols; i += blockDim.x)
        orow[i] = (xr[i] - mu) * rs * w[i] + b[i];
}

__global__ void ln_split_kernel(const float* __restrict__ x, const float* __restrict__ w,
                                const float* __restrict__ b,
                                bf16* __restrict__ hi, bf16* __restrict__ lo, int ncols) {
    __shared__ float s1[32], s2[32];
    const size_t row = blockIdx.x;
    const float* xr = x + row * (size_t)ncols;
    float mu, rs;
    ln_stats(xr, ncols, mu, rs, s1, s2);
    bf16* hrow = hi + row * (size_t)ncols;
    bf16* lrow = lo + row * (size_t)ncols;
    for (int i = threadIdx.x; i < ncols; i += blockDim.x) {
        float y = (xr[i] - mu) * rs * w[i] + b[i];
        bf16 hh = __float2bfloat16(y);
        hrow[i] = hh;
        lrow[i] = __float2bfloat16(y - __bfloat162float(hh));
    }
}

__global__ void split_kernel(const float* __restrict__ x,
                             bf16* __restrict__ hi, bf16* __restrict__ lo, int n) {
    int i = blockIdx.x * blockDim.x + threadIdx.x;
    if (i < n) {
        float v = x[i];
        bf16 h = __float2bfloat16(v);
        hi[i] = h;
        lo[i] = __float2bfloat16(v - __bfloat162float(h));
    }
}

__global__ void bias_kernel(const float* __restrict__ size_in, const float* __restrict__ mask,
                            float* __restrict__ bias, int n) {
    int i = blockIdx.x * blockDim.x + threadIdx.x;
    if (i < n) {
        float s = size_in[i];
        s = (s < 0.5f) ? 1.0f : s;
        bias[i] = logf(s) + mask[i];
    }
}

// ============================ SIMT GEMM (Q-proj only) ============================
#define TBM 64
#define TBN 64
#define TBK 16
#define SPAD 4

__global__ void __launch_bounds__(256)
gemm_nt_kernel(const float* __restrict__ A, int lda,
               const float* __restrict__ B, int ldb,
               float* __restrict__ C, int ldc,
               int M, int N, int K, float alpha, const float* __restrict__ bias_n) {
    __shared__ __align__(16) float As[TBK][TBM + SPAD];
    __shared__ __align__(16) float Bs[TBK][TBN + SPAD];
    const int m0 = blockIdx.y * TBM;
    const int n0 = blockIdx.x * TBN;
    const int t  = threadIdx.x;
    const int tx = t & 15, ty = t >> 4;
    float acc[4][4] = {};
    for (int k0 = 0; k0 < K; k0 += TBK) {
        {
            int col = t & 15, rowb = t >> 4;
            #pragma unroll
            for (int i = 0; i < 4; i++) {
                int rr = rowb + i * 16;
                As[col][rr] = A[(size_t)(m0 + rr) * lda + k0 + col];
            }
        }
        {
            int col = t & 15, rowb = t >> 4;
            #pragma unroll
            for (int i = 0; i < 4; i++) {
                int nn = rowb + i * 16;
                Bs[col][nn] = B[(size_t)(n0 + nn) * ldb + k0 + col];
            }
        }
        __syncthreads();
        #pragma unroll
        for (int kk = 0; kk < TBK; kk++) {
            float4 av = *reinterpret_cast<const float4*>(&As[kk][ty * 4]);
            float4 bv = *reinterpret_cast<const float4*>(&Bs[kk][tx * 4]);
            float a[4] = {av.x, av.y, av.z, av.w};
            float b[4] = {bv.x, bv.y, bv.z, bv.w};
            #pragma unroll
            for (int i = 0; i < 4; i++)
                #pragma unroll
                for (int j = 0; j < 4; j++)
                    acc[i][j] += a[i] * b[j];
        }
        __syncthreads();
    }
    #pragma unroll
    for (int i = 0; i < 4; i++) {
        int gm = m0 + ty * 4 + i;
        #pragma unroll
        for (int j = 0; j < 4; j++) {
            int gn = n0 + tx * 4 + j;
            float v = alpha * acc[i][j];
            if (bias_n) v += bias_n[gn];
            C[(size_t)gm * ldc + gn] = v;
        }
    }
}

// ============================ launch ============================
extern "C" void kernel_launch(void* const* d_in, const int* in_sizes, int n_in,
                              void* d_out, int out_size) {
    const float* x     = (const float*)d_in[0];
    const float* sizei = (const float*)d_in[1];
    const float* amask = (const float*)d_in[2];
    const float* query = (const float*)d_in[3];
    const float* ln_q_w = (const float*)d_in[4];
    const float* ln_q_b = (const float*)d_in[5];
    const float* ln_k_w = (const float*)d_in[6];
    const float* ln_k_b = (const float*)d_in[7];
    const float* Wq = (const float*)d_in[8];
    const float* Wk = (const float*)d_in[9];
    const float* Wv = (const float*)d_in[10];
    const float* bq = (const float*)d_in[11];
    const float* bk = (const float*)d_in[12];
    const float* bv = (const float*)d_in[13];
    const float* Wo = (const float*)d_in[14];
    const float* bo = (const float*)d_in[15];
    float* out = (float*)d_out;

    bf16 *xhi, *xlo, *wkhi, *wklo, *wvhi, *wvlo, *wohi, *wolo;
    bf16 *khhi, *khlo, *vhhi, *vhlo, *qhhi, *qhlo, *aohi, *aolo;
    float *qln, *qh, *bias;
    cudaGetSymbolAddress((void**)&xhi, g_xhi);
    cudaGetSymbolAddress((void**)&xlo, g_xlo);
    cudaGetSymbolAddress((void**)&wkhi, g_wkhi);
    cudaGetSymbolAddress((void**)&wklo, g_wklo);
    cudaGetSymbolAddress((void**)&wvhi, g_wvhi);
    cudaGetSymbolAddress((void**)&wvlo, g_wvlo);
    cudaGetSymbolAddress((void**)&wohi, g_wohi);
    cudaGetSymbolAddress((void**)&wolo, g_wolo);
    cudaGetSymbolAddress((void**)&khhi, g_khhi);
    cudaGetSymbolAddress((void**)&khlo, g_khlo);
    cudaGetSymbolAddress((void**)&vhhi, g_vhhi);
    cudaGetSymbolAddress((void**)&vhlo, g_vhlo);
    cudaGetSymbolAddress((void**)&qhhi, g_qhhi);
    cudaGetSymbolAddress((void**)&qhlo, g_qhlo);
    cudaGetSymbolAddress((void**)&aohi, g_aohi);
    cudaGetSymbolAddress((void**)&aolo, g_aolo);
    cudaGetSymbolAddress((void**)&qln, g_qln);
    cudaGetSymbolAddress((void**)&qh, g_qh);
    cudaGetSymbolAddress((void**)&bias, g_bias);

    cudaFuncSetAttribute(kv_gemm,    cudaFuncAttributeMaxDynamicSharedMemorySize, G3_SMEM);
    cudaFuncSetAttribute(oproj_gemm, cudaFuncAttributeMaxDynamicSharedMemorySize, G3_SMEM);
    cudaFuncSetAttribute(fa_kernel,  cudaFuncAttributeMaxDynamicSharedMemorySize, FA_SMEM);

    const float scale = 0.10206207261596575f;  // 1/sqrt(96)

    // launch order: index 3 (ncu-profiled) = kv_gemm(K)
    ln_split_kernel<<<MROWS, 256>>>(x, ln_k_w, ln_k_b, xhi, xlo, CTXD);               // 0
    split_kernel<<<(DMODEL * CTXD + 255) / 256, 256>>>(Wk, wkhi, wklo, DMODEL * CTXD); // 1
    split_kernel<<<(DMODEL * CTXD + 255) / 256, 256>>>(Wv, wvhi, wvlo, DMODEL * CTXD); // 2
    {
        dim3 grid(DMODEL / 128, MROWS / 128);
        kv_gemm<<<grid, 256, G3_SMEM>>>(xhi, xlo, wkhi, wklo, bk, khhi, khlo);         // 3 (profiled)
        kv_gemm<<<grid, 256, G3_SMEM>>>(xhi, xlo, wvhi, wvlo, bv, vhhi, vhlo);         // 4
    }
    ln_kernel<<<NQ, 256>>>(query, ln_q_w, ln_q_b, qln, DMODEL);                        // 5
    split_kernel<<<(DMODEL * DMODEL + 255) / 256, 256>>>(Wo, wohi, wolo, DMODEL * DMODEL); // 6
    bias_kernel<<<(MROWS + 255) / 256, 256>>>(sizei, amask, bias, MROWS);              // 7
    gemm_nt_kernel<<<dim3(DMODEL / TBN, NQ / TBM), 256>>>(                             // 8
        qln, DMODEL, Wq, DMODEL, qh, DMODEL, NQ, DMODEL, DMODEL, 1.0f, bq);
    split_kernel<<<(NQ * DMODEL + 255) / 256, 256>>>(qh, qhhi, qhlo, NQ * DMODEL);     // 9

    fa_kernel<<<dim3(NQ / 128, NZ), 256, FA_SMEM>>>(                                   // 10
        qhhi, qhlo, khhi, khlo, vhhi, vhlo, bias, scale, aohi, aolo);

    oproj_gemm<<<dim3(DMODEL / 128, BATCH * NQ / 128), 256, G3_SMEM>>>(                // 11
        aohi, aolo, wohi, wolo, bo, out);
}